// round 8
// baseline (speedup 1.0000x reference)
#include <cuda_runtime.h>
#include <cuda_bf16.h>
#include <math.h>
#include <stdint.h>

#define BB 2
#define SS 2048
#define DD 1024
#define NH 16
#define DH 64
#define NE 8
#define FF 4096
#define TT (BB*SS)   // 4096 tokens
#define NMAIN (TT*DD)

typedef __nv_bfloat16 bf16;

// ---------------- scratch (static device globals; no cudaMalloc allowed) ----
__device__ bf16  g_xnh[TT*DD],  g_xnl[TT*DD];          // rmsnorm1 out, split
__device__ float g_xn2[TT*DD];                          // rmsnorm2 out fp32 (router)
__device__ bf16  g_xn2h[TT*DD], g_xn2l[TT*DD];          // rmsnorm2 out, split
__device__ bf16  g_qkvh[3][(size_t)TT*DD];              // q,k,v hi  [B,H,S,Dh]
__device__ bf16  g_qkvl[3][(size_t)TT*DD];              // q,k,v lo  [B,H,S,Dh]
__device__ bf16  g_ctxh[TT*DD], g_ctxl[TT*DD];          // attention ctx, split
__device__ float g_x2[TT*DD];                           // x + attn_out
__device__ bf16  g_wpth[4*DD*DD], g_wptl[4*DD*DD];      // wq,wk,wv,wo transposed split
__device__ bf16  g_w1th[(size_t)NE*DD*FF], g_w1tl[(size_t)NE*DD*FF];
__device__ bf16  g_w2th[(size_t)NE*DD*FF], g_w2tl[(size_t)NE*DD*FF];
__device__ bf16  g_Hh[(size_t)NE*TT*FF], g_Hl[(size_t)NE*TT*FF];  // gelu(h) split
__device__ float g_Y[(size_t)NE*TT*DD];
__device__ float g_probs[TT*NE];
__device__ float g_zz[TT];
__device__ int   g_cnt[NE];
__device__ int   g_rowlist[NE*TT];
__device__ int   g_slot_e[2*TT];
__device__ int   g_slot_r[2*TT];
__device__ float g_slot_w[2*TT];

// ---------------- PTX helpers ----------------
__device__ __forceinline__ uint32_t smem_u32(const void* p) {
    uint32_t a;
    asm("{ .reg .u64 t; cvta.to.shared.u64 t, %1; cvt.u32.u64 %0, t; }" : "=r"(a) : "l"(p));
    return a;
}
__device__ __forceinline__ uint32_t elect1() {
    uint32_t p;
    asm volatile("{\n.reg .pred p;\nelect.sync _|p, 0xFFFFFFFF;\nselp.b32 %0, 1, 0, p;\n}" : "=r"(p));
    return p;
}
__device__ __forceinline__ void mbar_init(uint32_t a, uint32_t n) {
    asm volatile("mbarrier.init.shared.b64 [%0], %1;" :: "r"(a), "r"(n) : "memory");
}
__device__ __forceinline__ void mbar_wait(uint32_t a, uint32_t par) {
    asm volatile(
        "{\n.reg .pred P;\n"
        "LW%=:\n"
        "mbarrier.try_wait.parity.acquire.cta.shared::cta.b64 P, [%0], %1, 0x989680;\n"
        "@P bra LD%=;\n"
        "bra LW%=;\n"
        "LD%=:\n}"
        :: "r"(a), "r"(par) : "memory");
}
// K-major SW128 descriptor (row = 128B)
__device__ __forceinline__ uint64_t mk_desc(uint32_t addr) {
    return ((uint64_t)2 << 61) | ((uint64_t)1 << 46) | ((uint64_t)64 << 32)
         | ((uint64_t)1 << 16) | ((addr >> 4) & 0x3FFF);
}
__device__ __forceinline__ void tc_commit(uint32_t mbar) {
#if defined(__CUDA_ARCH_FEAT_SM103_ALL)
    asm volatile("tcgen05.commit.cta_group::1.mbarrier::arrive::one.shared::cluster.b64 [%0];"
                 :: "r"(mbar) : "memory");
#endif
}
__device__ __forceinline__ void mma_f16_ss(uint32_t d, uint64_t ad, uint64_t bd,
                                           uint32_t idesc, uint32_t en) {
#if defined(__CUDA_ARCH_FEAT_SM103_ALL)
    asm volatile(
        "{\n.reg .pred p;\n"
        "setp.ne.u32 p, %4, 0;\n"
        "tcgen05.mma.cta_group::1.kind::f16 [%0], %1, %2, %3, {%5, %5, %5, %5}, p;\n}"
        :: "r"(d), "l"(ad), "l"(bd), "r"(idesc), "r"(en), "r"(0u) : "memory");
#endif
}

#if defined(__CUDA_ARCH_FEAT_SM103_ALL)
#define TC_ALLOC(sbaddr, n) \
    asm volatile("tcgen05.alloc.cta_group::1.sync.aligned.shared::cta.b32 [%0], %1;" \
                 :: "r"(sbaddr), "r"((uint32_t)(n)) : "memory")
#define TC_RELINQ() \
    asm volatile("tcgen05.relinquish_alloc_permit.cta_group::1.sync.aligned;")
#define TC_DEALLOC(t, n) \
    asm volatile("tcgen05.dealloc.cta_group::1.sync.aligned.b32 %0, %1;" :: "r"(t), "r"((uint32_t)(n)))
#define TC_FENCE_AFTER()  asm volatile("tcgen05.fence::after_thread_sync;" ::: "memory")
#define TC_FENCE_BEFORE() asm volatile("tcgen05.fence::before_thread_sync;" ::: "memory")
#define TC_WAIT_LD()      asm volatile("tcgen05.wait::ld.sync.aligned;" ::: "memory")
#define TC_LD_X32(r, ta) \
    asm volatile( \
        "tcgen05.ld.sync.aligned.32x32b.x32.b32 " \
        "{%0, %1, %2, %3, %4, %5, %6, %7, " \
        " %8, %9, %10, %11, %12, %13, %14, %15, " \
        " %16, %17, %18, %19, %20, %21, %22, %23, " \
        " %24, %25, %26, %27, %28, %29, %30, %31}, [%32];" \
        : "=r"((r)[0]),  "=r"((r)[1]),  "=r"((r)[2]),  "=r"((r)[3]), \
          "=r"((r)[4]),  "=r"((r)[5]),  "=r"((r)[6]),  "=r"((r)[7]), \
          "=r"((r)[8]),  "=r"((r)[9]),  "=r"((r)[10]), "=r"((r)[11]), \
          "=r"((r)[12]), "=r"((r)[13]), "=r"((r)[14]), "=r"((r)[15]), \
          "=r"((r)[16]), "=r"((r)[17]), "=r"((r)[18]), "=r"((r)[19]), \
          "=r"((r)[20]), "=r"((r)[21]), "=r"((r)[22]), "=r"((r)[23]), \
          "=r"((r)[24]), "=r"((r)[25]), "=r"((r)[26]), "=r"((r)[27]), \
          "=r"((r)[28]), "=r"((r)[29]), "=r"((r)[30]), "=r"((r)[31]) \
        : "r"(ta))
#endif

__device__ __forceinline__ float gelu_tanh(float x) {
    float x3 = x * x * x;
    return 0.5f * x * (1.f + tanhf(0.7978845608028654f * (x + 0.044715f * x3)));
}
__device__ __forceinline__ uint32_t pack_bf2(float a, float b) {
    return ((uint32_t)__bfloat16_as_ushort(__float2bfloat16(b)) << 16)
         |  (uint32_t)__bfloat16_as_ushort(__float2bfloat16(a));
}

// ---------------- rmsnorm (writes fp32 optional + bf16 hi/lo) ----------------
__global__ void rmsnorm_kernel(const float* __restrict__ x, const float* __restrict__ w,
                               float* __restrict__ yf, bf16* __restrict__ yh, bf16* __restrict__ yl)
{
    int row = blockIdx.x;
    int tid = threadIdx.x;
    const float* xr = x + (size_t)row * DD;
    float s = 0.f;
    for (int d = tid; d < DD; d += 256) { float v = xr[d]; s += v * v; }
    __shared__ float red[256];
    red[tid] = s; __syncthreads();
    for (int o = 128; o > 0; o >>= 1) { if (tid < o) red[tid] += red[tid + o]; __syncthreads(); }
    float inv = rsqrtf(red[0] / (float)DD + 1e-6f);
    size_t base = (size_t)row * DD;
    for (int d = tid; d < DD; d += 256) {
        float v = xr[d] * inv * w[d];
        if (yf) yf[base + d] = v;
        bf16 h = __float2bfloat16(v);
        yh[base + d] = h;
        yl[base + d] = __float2bfloat16(v - __bfloat162float(h));
    }
}

// ---------------- weight transpose + bf16 split (vectorized) ----------------
__global__ void wt_convert_kernel(const float* __restrict__ W,
                                  bf16* __restrict__ Th, bf16* __restrict__ Tl,
                                  int K, int N)
{
    __shared__ float tile[64][68];
    size_t zoff = (size_t)blockIdx.z * K * N;
    int n0 = blockIdx.x * 64, k0 = blockIdx.y * 64;
    int tx = threadIdx.x & 15, ty = threadIdx.x >> 4;   // 16x16
#pragma unroll
    for (int i = 0; i < 4; i++) {
        int r = ty + 16 * i;
        float4 v = *(const float4*)(W + zoff + (size_t)(k0 + r) * N + n0 + tx * 4);
        *(float4*)&tile[r][tx * 4] = v;
    }
    __syncthreads();
#pragma unroll
    for (int i = 0; i < 4; i++) {
        int n = ty + 16 * i;
        int kk = tx * 4;
        float v0 = tile[kk + 0][n], v1 = tile[kk + 1][n];
        float v2 = tile[kk + 2][n], v3 = tile[kk + 3][n];
        bf16 h0 = __float2bfloat16(v0), h1 = __float2bfloat16(v1);
        bf16 h2 = __float2bfloat16(v2), h3 = __float2bfloat16(v3);
        float l0 = v0 - __bfloat162float(h0), l1 = v1 - __bfloat162float(h1);
        float l2 = v2 - __bfloat162float(h2), l3 = v3 - __bfloat162float(h3);
        size_t idx = zoff + (size_t)(n0 + n) * K + k0 + kk;
        uint2 ph, pl;
        ph.x = ((uint32_t)__bfloat16_as_ushort(h1) << 16) | __bfloat16_as_ushort(h0);
        ph.y = ((uint32_t)__bfloat16_as_ushort(h3) << 16) | __bfloat16_as_ushort(h2);
        pl.x = pack_bf2(l0, l1);
        pl.y = pack_bf2(l2, l3);
        *(uint2*)(Th + idx) = ph;
        *(uint2*)(Tl + idx) = pl;
    }
}

// ---------------- GEMM modes ----------------
#define GM_QKV  1
#define GM_RES  2
#define GM_MOE1 3
#define GM_MOE2 4
// N=256 tiles: per-chunk buffer {Ah 16K, Al 16K, Bh 32K, Bl 32K} = 96 KB, x2
#define BUF_BYTES 98304
#define G_SMEM  (1024 + 2 * BUF_BYTES)   // 197632 B

// scalar store (fallback path only)
template<int MODE>
__device__ __forceinline__ void store_elem(int e, int N, int row, int col, float v,
        float* __restrict__ Cf, const float* __restrict__ Res,
        bf16* __restrict__ Ch, bf16* __restrict__ Cl)
{
    if (MODE == GM_QKV) {
        int b = row >> 11, s5 = row & (SS - 1);
        int h = col >> 6, dh = col & 63;
        size_t o = (((size_t)(b * NH + h)) * SS + s5) * DH + dh;
        bf16 hh = __float2bfloat16(v);
        g_qkvh[e][o] = hh;
        g_qkvl[e][o] = __float2bfloat16(v - __bfloat162float(hh));
    } else if (MODE == GM_RES) {
        size_t o = (size_t)row * N + col;
        Cf[o] = v + Res[o];
    } else if (MODE == GM_MOE1) {
        size_t o = ((size_t)e * TT + row) * N + col;
        float g = gelu_tanh(v);
        bf16 h = __float2bfloat16(g);
        Ch[o] = h;
        Cl[o] = __float2bfloat16(g - __bfloat162float(h));
    } else {
        Cf[((size_t)e * TT + row) * N + col] = v;
    }
}

// ---------------- tcgen05 GEMM: C[128x256] tiles, 3-term bf16 split,
//                  cp.async double-buffered pipeline, N=256 MMAs ------------
template<int MODE>
__global__ void __launch_bounds__(256, 1)
tc_gemm(const bf16* __restrict__ Ah, const bf16* __restrict__ Al,
        const bf16* __restrict__ Bh0, const bf16* __restrict__ Bl0,
        float* __restrict__ Cf, const float* __restrict__ Res,
        bf16* __restrict__ Ch, bf16* __restrict__ Cl,
        int M, int N, int K)
{
#if defined(__CUDA_ARCH__)
    extern __shared__ char sm[];
    int tid = threadIdx.x;
    int e  = blockIdx.z;
    int m0 = blockIdx.y * 128, n0 = blockIdx.x * 256;
    int Me = M;
    const bf16* Bh = Bh0;
    const bf16* Bl = Bl0;
    if (MODE == GM_MOE1 || MODE == GM_MOE2) {
        Me = g_cnt[e];
        if (m0 >= Me) return;
        Bh += (size_t)e * (size_t)K * N; Bl += (size_t)e * (size_t)K * N;
    } else if (MODE == GM_QKV) {
        Bh += (size_t)e * (size_t)K * N; Bl += (size_t)e * (size_t)K * N;
    }

#if defined(__CUDA_ARCH_FEAT_SM103_ALL)
    uint32_t sb = smem_u32(sm);
    int wid = tid >> 5, lid = tid & 31;
    int nk = K / 64;

    // fill chunk kc into buffer bufi via cp.async (384 row tasks: 128 A + 256 B)
    auto issue_fill = [&](int kc, int bufi) {
        uint32_t tb = sb + 1024 + (uint32_t)bufi * BUF_BYTES;
        for (int task = tid; task < 384; task += 256) {
            const bf16 *sh, *sl;
            uint32_t regionH, regionL;
            int row;
            bool val = true;
            if (task < 128) {
                int gr = m0 + task;
                val = gr < Me;
                size_t ri = 0;
                if (val) {
                    if (MODE == GM_MOE1)      ri = (size_t)g_rowlist[e * TT + gr];
                    else if (MODE == GM_MOE2) ri = (size_t)e * TT + gr;
                    else                      ri = (size_t)gr;
                }
                sh = Ah + ri * (size_t)K;
                sl = Al + ri * (size_t)K;
                regionH = tb; regionL = tb + 16384;
                row = task;
            } else {
                row = task - 128;
                sh = Bh + (size_t)(n0 + row) * K;
                sl = Bl + (size_t)(n0 + row) * K;
                regionH = tb + 32768; regionL = tb + 65536;
            }
            const char* srcH = (const char*)(sh + kc * 64);
            const char* srcL = (const char*)(sl + kc * 64);
            uint32_t sz = val ? 16u : 0u;
#pragma unroll
            for (int j = 0; j < 8; j++) {
                uint32_t off = (uint32_t)row * 128u + j * 16u;
                uint32_t swz = off ^ ((off >> 3) & 0x70);
                asm volatile("cp.async.cg.shared.global [%0], [%1], 16, %2;"
                             :: "r"(regionH + swz), "l"(srcH + j * 16), "r"(sz) : "memory");
                asm volatile("cp.async.cg.shared.global [%0], [%1], 16, %2;"
                             :: "r"(regionL + swz), "l"(srcL + j * 16), "r"(sz) : "memory");
            }
        }
        asm volatile("cp.async.commit_group;" ::: "memory");
    };

    // prologue: start chunks 0 and 1 immediately (overlaps TMEM alloc)
    issue_fill(0, 0);
    if (nk > 1) issue_fill(1, 1);

    if (wid == 0) { TC_ALLOC(sb, 256); TC_RELINQ(); }
    if (tid == 0) { mbar_init(sb + 8, 1); mbar_init(sb + 16, 1); }
    __syncthreads();
    uint32_t tmem;
    asm volatile("ld.shared.b32 %0, [%1];" : "=r"(tmem) : "r"(sb));

    const uint32_t IDESC = (1u << 4) | (1u << 7) | (1u << 10) | (32u << 17) | (8u << 24);
    int ph0 = 0, ph1 = 0;
    for (int kc = 0; kc < nk; kc++) {
        int b = kc & 1;
        if (kc >= 1 && kc + 1 < nk) {
            int nb = 1 - b;
            // buffer nb was consumed by chunk kc-1's MMAs; wait then refill
            if (nb == 0) { mbar_wait(sb + 8,  (uint32_t)(ph0 & 1)); ph0++; }
            else         { mbar_wait(sb + 16, (uint32_t)(ph1 & 1)); ph1++; }
            issue_fill(kc + 1, nb);
        }
        if (kc + 1 < nk) asm volatile("cp.async.wait_group 1;" ::: "memory");
        else             asm volatile("cp.async.wait_group 0;" ::: "memory");
        asm volatile("fence.proxy.async.shared::cta;" ::: "memory");
        __syncthreads();
        if (wid == 0 && elect1()) {
            uint32_t tb = sb + 1024 + (uint32_t)b * BUF_BYTES;
            uint64_t dAh = mk_desc(tb);
            uint64_t dAl = mk_desc(tb + 16384);
            uint64_t dBh = mk_desc(tb + 32768);
            uint64_t dBl = mk_desc(tb + 65536);
#pragma unroll
            for (int s = 0; s < 4; s++) {
                uint32_t en0 = (kc == 0 && s == 0) ? 0u : 1u;
                mma_f16_ss(tmem, dAh + 2 * s, dBh + 2 * s, IDESC, en0);
                mma_f16_ss(tmem, dAh + 2 * s, dBl + 2 * s, IDESC, 1u);
                mma_f16_ss(tmem, dAl + 2 * s, dBh + 2 * s, IDESC, 1u);
            }
            tc_commit(sb + 8 + b * 8);
        }
    }
    {
        int lb = (nk - 1) & 1;
        if (lb == 0) mbar_wait(sb + 8,  (uint32_t)(ph0 & 1));
        else         mbar_wait(sb + 16, (uint32_t)(ph1 & 1));
    }
    TC_FENCE_AFTER();

    // ---- staged epilogue: two 128-col passes, TMEM -> smem -> coalesced ----
    int rw = wid & 3, cw = wid >> 2;
    int rows_here = Me - m0; if (rows_here > 128) rows_here = 128;
    float* Cs = (float*)(sm + 1024);
#pragma unroll 1
    for (int p = 0; p < 2; p++) {
        uint32_t d0[32], d1[32];
        TC_LD_X32(d0, tmem + p * 128 + cw * 64);
        TC_LD_X32(d1, tmem + p * 128 + cw * 64 + 32);
        TC_WAIT_LD();
        TC_FENCE_BEFORE();
        __syncthreads();
        {
            int rr = rw * 32 + lid;
            int cb = cw * 64;
#pragma unroll
            for (int j = 0; j < 32; j++) {
                Cs[rr * 129 + cb + j]      = __uint_as_float(d0[j]);
                Cs[rr * 129 + cb + 32 + j] = __uint_as_float(d1[j]);
            }
        }
        __syncthreads();
#pragma unroll 4
        for (int it = 0; it < 16; it++) {
            int idx4 = (it * 256 + tid) * 4;
            int rr = idx4 >> 7, cc = idx4 & 127;
            if (rr >= rows_here) continue;
            float v0 = Cs[rr * 129 + cc + 0];
            float v1 = Cs[rr * 129 + cc + 1];
            float v2 = Cs[rr * 129 + cc + 2];
            float v3 = Cs[rr * 129 + cc + 3];
            int colb = n0 + p * 128 + cc;
            if (MODE == GM_RES) {
                size_t o = (size_t)(m0 + rr) * N + colb;
                float4 rs = *(const float4*)(Res + o);
                *(float4*)(Cf + o) = make_float4(v0 + rs.x, v1 + rs.y, v2 + rs.z, v3 + rs.w);
            } else if (MODE == GM_MOE2) {
                size_t o = ((size_t)e * TT + m0 + rr) * N + colb;
                *(float4*)(Cf + o) = make_float4(v0, v1, v2, v3);
            } else if (MODE == GM_MOE1) {
                size_t o = ((size_t)e * TT + m0 + rr) * N + colb;
                float g0 = gelu_tanh(v0), g1 = gelu_tanh(v1);
                float g2 = gelu_tanh(v2), g3 = gelu_tanh(v3);
                bf16 h0 = __float2bfloat16(g0), h1 = __float2bfloat16(g1);
                bf16 h2 = __float2bfloat16(g2), h3 = __float2bfloat16(g3);
                uint2 ph, pl;
                ph.x = ((uint32_t)__bfloat16_as_ushort(h1) << 16) | __bfloat16_as_ushort(h0);
                ph.y = ((uint32_t)__bfloat16_as_ushort(h3) << 16) | __bfloat16_as_ushort(h2);
                pl.x = pack_bf2(g0 - __bfloat162float(h0), g1 - __bfloat162float(h1));
                pl.y = pack_bf2(g2 - __bfloat162float(h2), g3 - __bfloat162float(h3));
                *(uint2*)(Ch + o) = ph;
                *(uint2*)(Cl + o) = pl;
            } else { // GM_QKV -> bf16 hi/lo [B,H,S,Dh]
                int row = m0 + rr;
                int b2 = row >> 11, s5 = row & (SS - 1);
                int h = colb >> 6, dh = colb & 63;
                size_t o = (((size_t)(b2 * NH + h)) * SS + s5) * DH + dh;
                bf16 h0 = __float2bfloat16(v0), h1 = __float2bfloat16(v1);
                bf16 h2 = __float2bfloat16(v2), h3 = __float2bfloat16(v3);
                uint2 ph, pl;
                ph.x = ((uint32_t)__bfloat16_as_ushort(h1) << 16) | __bfloat16_as_ushort(h0);
                ph.y = ((uint32_t)__bfloat16_as_ushort(h3) << 16) | __bfloat16_as_ushort(h2);
                pl.x = pack_bf2(v0 - __bfloat162float(h0), v1 - __bfloat162float(h1));
                pl.y = pack_bf2(v2 - __bfloat162float(h2), v3 - __bfloat162float(h3));
                *(uint2*)(g_qkvh[e] + o) = ph;
                *(uint2*)(g_qkvl[e] + o) = pl;
            }
        }
        __syncthreads();
    }
    if (wid == 0) { TC_DEALLOC(tmem, 256); }

#else
    // ---- SIMT fallback (base-arch pass): two 128-col halves ----
    float* As = (float*)sm;
    float* Bs = As + 16 * 128;
    int tx = tid & 15, ty = tid >> 4;
    for (int half = 0; half < 2; half++) {
        int n0h = n0 + half * 128;
        float acc[8][8];
#pragma unroll
        for (int i = 0; i < 8; i++)
#pragma unroll
            for (int j = 0; j < 8; j++) acc[i][j] = 0.f;
        for (int k0 = 0; k0 < K; k0 += 16) {
            __syncthreads();
            for (int l = tid; l < 16 * 128; l += 256) {
                int kk = l >> 7, rr = l & 127;
                int gr = m0 + rr;
                float av = 0.f;
                if (gr < Me) {
                    size_t ri;
                    if (MODE == GM_MOE1)      ri = (size_t)g_rowlist[e * TT + gr];
                    else if (MODE == GM_MOE2) ri = (size_t)e * TT + gr;
                    else                      ri = (size_t)gr;
                    av = __bfloat162float(Ah[ri * (size_t)K + k0 + kk])
                       + __bfloat162float(Al[ri * (size_t)K + k0 + kk]);
                }
                As[kk * 128 + rr] = av;
                Bs[kk * 128 + rr] = __bfloat162float(Bh[(size_t)(n0h + rr) * K + k0 + kk])
                                  + __bfloat162float(Bl[(size_t)(n0h + rr) * K + k0 + kk]);
            }
            __syncthreads();
            for (int kk = 0; kk < 16; kk++) {
                float ar[8], br[8];
#pragma unroll
                for (int i = 0; i < 8; i++) ar[i] = As[kk * 128 + ty * 8 + i];
#pragma unroll
                for (int j = 0; j < 8; j++) br[j] = Bs[kk * 128 + tx * 8 + j];
#pragma unroll
                for (int i = 0; i < 8; i++)
#pragma unroll
                    for (int j = 0; j < 8; j++) acc[i][j] = fmaf(ar[i], br[j], acc[i][j]);
            }
        }
#pragma unroll
        for (int i = 0; i < 8; i++) {
            int row = m0 + ty * 8 + i;
            if (row >= Me) continue;
#pragma unroll
            for (int j = 0; j < 8; j++)
                store_elem<MODE>(e, N, row, n0h + tx * 8 + j, acc[i][j], Cf, Res, Ch, Cl);
        }
        __syncthreads();
    }
#endif
#endif // __CUDA_ARCH__
}

// ---------------- tcgen05 flash attention, cp.async KV prefetch ------------
#define SM_Q   1024
#define SM_K   33792
#define SM_VST 66560
#define SM_VT  99328
#define SM_P   132096
#define ATT_SMEM 197632

__global__ void __launch_bounds__(256, 1)
tc_attn(bf16* __restrict__ outh, bf16* __restrict__ outl)
{
#if defined(__CUDA_ARCH__)
    extern __shared__ char sm[];
    int tid = threadIdx.x;
    int bh = blockIdx.x;
    int qt = blockIdx.y;

#if defined(__CUDA_ARCH_FEAT_SM103_ALL)
    uint32_t sb = smem_u32(sm);
    int wid = tid >> 5, lane = tid & 31;

    // async fill of K (swizzled) + V (linear) hi/lo for chunk kt
    auto fill_kv = [&](int kt) {
#pragma unroll
        for (int i = 0; i < 2; i++) {
            int task = tid + i * 256;
            int arr = task >> 7, r = task & 127;
            const bf16* src;
            uint32_t dstb;
            if (arr == 0)      { src = g_qkvh[1]; dstb = sb + SM_K; }
            else if (arr == 1) { src = g_qkvl[1]; dstb = sb + SM_K + 16384; }
            else if (arr == 2) { src = g_qkvh[2]; dstb = sb + SM_VST; }
            else               { src = g_qkvl[2]; dstb = sb + SM_VST + 16384; }
            const char* s4 = (const char*)(src + ((size_t)bh * SS + kt * 128 + r) * DH);
            if (arr < 2) {
#pragma unroll
                for (int j = 0; j < 8; j++) {
                    uint32_t off = (uint32_t)r * 128u + j * 16u;
                    uint32_t swz = off ^ ((off >> 3) & 0x70);
                    asm volatile("cp.async.cg.shared.global [%0], [%1], 16;"
                                 :: "r"(dstb + swz), "l"(s4 + j * 16) : "memory");
                }
            } else {
#pragma unroll
                for (int j = 0; j < 8; j++)
                    asm volatile("cp.async.cg.shared.global [%0], [%1], 16;"
                                 :: "r"(dstb + (uint32_t)r * 128u + j * 16u), "l"(s4 + j * 16) : "memory");
            }
        }
        asm volatile("cp.async.commit_group;" ::: "memory");
    };

    // prologue: kick off chunk 0 loads immediately
    fill_kv(0);

    if (wid == 0) { TC_ALLOC(sb, 256); TC_RELINQ(); }
    if (tid == 0) { mbar_init(sb + 8, 1); mbar_init(sb + 16, 1); }
    __syncthreads();
    uint32_t tmem;
    asm volatile("ld.shared.b32 %0, [%1];" : "=r"(tmem) : "r"(sb));

    // load Q tile (hi/lo): threads 0-127 hi rows, 128-255 lo rows
    {
        int r = tid & 127;
        const bf16* src = (tid < 128 ? g_qkvh[0] : g_qkvl[0])
                        + ((size_t)bh * SS + qt * 128 + r) * DH;
        char* dst = sm + SM_Q + (tid < 128 ? 0 : 16384);
        const uint4* s4 = (const uint4*)src;
#pragma unroll
        for (int j = 0; j < 8; j++) {
            uint32_t off = (uint32_t)r * 128u + j * 16u;
            uint32_t swz = off ^ ((off >> 3) & 0x70);
            *(uint4*)(dst + swz) = s4[j];
        }
    }

    const uint32_t IDESC_S = (1u << 4) | (1u << 7) | (1u << 10) | (16u << 17) | (8u << 24);
    const uint32_t IDESC_O = (1u << 4) | (1u << 7) | (1u << 10) | (8u << 17) | (8u << 24);
    int sph = 0, oph = 0;
    float lpart = 0.f;
    const int NKT = SS / 128;

    for (int kt = 0; kt < NKT; kt++) {
        if (kt > 0) { mbar_wait(sb + 16, (uint32_t)(oph & 1)); oph++; }  // PV of kt-1 done
        asm volatile("cp.async.wait_group 0;" ::: "memory");             // KV chunk kt arrived
        asm volatile("fence.proxy.async.shared::cta;" ::: "memory");
        __syncthreads();

        // scores: S = Qh*Kh + Qh*Kl + Ql*Kh (M=128,N=128,K=64)
        if (wid == 0 && elect1()) {
            uint64_t dQh = mk_desc(sb + SM_Q);
            uint64_t dQl = mk_desc(sb + SM_Q + 16384);
            uint64_t dKh = mk_desc(sb + SM_K);
            uint64_t dKl = mk_desc(sb + SM_K + 16384);
#pragma unroll
            for (int ks = 0; ks < 4; ks++) {
                mma_f16_ss(tmem, dQh + 2 * ks, dKh + 2 * ks, IDESC_S, ks == 0 ? 0u : 1u);
                mma_f16_ss(tmem, dQh + 2 * ks, dKl + 2 * ks, IDESC_S, 1u);
                mma_f16_ss(tmem, dQl + 2 * ks, dKh + 2 * ks, IDESC_S, 1u);
            }
            tc_commit(sb + 8);
        }

        // transpose V (overlaps S MMA): VT block kb = [64 d-rows][64 s], SW128
        {
            int a  = tid >> 7;
            int i2 = tid & 127;
            int d  = i2 >> 1;
            int shb = i2 & 1;
            const unsigned short* vs = (const unsigned short*)(sm + SM_VST + a * 16384);
            char* vt = sm + SM_VT + a * 16384 + shb * 8192;
#pragma unroll
            for (int m = 0; m < 32; m++) {
                int s0 = shb * 64 + 2 * m;
                uint32_t u = (uint32_t)vs[s0 * 64 + d]
                           | ((uint32_t)vs[(s0 + 1) * 64 + d] << 16);
                uint32_t off = (uint32_t)d * 128u + m * 4u;
                uint32_t swz = off ^ ((off >> 3) & 0x70);
                *(uint32_t*)(vt + swz) = u;
            }
        }
        asm volatile("fence.proxy.async.shared::cta;" ::: "memory");
        __syncthreads();                                  // VT visible; VST free

        mbar_wait(sb + 8, (uint32_t)(sph & 1)); sph++;    // S MMA done; K smem free
        TC_FENCE_AFTER();

        // prefetch next KV chunk, overlapping exp epilogue + PV MMA
        if (kt + 1 < NKT) fill_kv(kt + 1);

        // read S, exp, accumulate l, write P (bf16 hi/lo) to smem
        {
            int rw = wid & 3, cw = wid >> 2;
            uint32_t s0[32], s1[32];
            TC_LD_X32(s0, tmem + cw * 64);
            TC_LD_X32(s1, tmem + cw * 64 + 32);
            TC_WAIT_LD();
            TC_FENCE_BEFORE();
            int r = rw * 32 + lane;
            char* pbh = sm + SM_P + cw * 16384;
            char* pbl = sm + SM_P + 32768 + cw * 16384;
#pragma unroll
            for (int m = 0; m < 32; m++) {
                int c0 = 2 * m, c1 = 2 * m + 1;
                float a = __uint_as_float(c0 < 32 ? s0[c0] : s1[c0 - 32]);
                float b = __uint_as_float(c1 < 32 ? s0[c1] : s1[c1 - 32]);
                float pa = __expf(a * 0.125f);
                float pb = __expf(b * 0.125f);
                lpart += pa + pb;
                bf16 ha = __float2bfloat16(pa), hb = __float2bfloat16(pb);
                float la = pa - __bfloat162float(ha), lb = pb - __bfloat162float(hb);
                uint32_t uph = ((uint32_t)__bfloat16_as_ushort(hb) << 16) | __bfloat16_as_ushort(ha);
                uint32_t upl = pack_bf2(la, lb);
                uint32_t off = (uint32_t)r * 128u + m * 4u;
                uint32_t swz = off ^ ((off >> 3) & 0x70);
                *(uint32_t*)(pbh + swz) = uph;
                *(uint32_t*)(pbl + swz) = upl;
            }
        }
        asm volatile("fence.proxy.async.shared::cta;" ::: "memory");
        __syncthreads();

        // O += Ph*VTh + Pl*VTh + Ph*VTl (plain K-major, M=128,N=64,K=64 per kb)
        if (wid == 0 && elect1()) {
#pragma unroll
            for (int kb = 0; kb < 2; kb++) {
                uint64_t dPh = mk_desc(sb + SM_P + kb * 16384);
                uint64_t dPl = mk_desc(sb + SM_P + 32768 + kb * 16384);
                uint64_t dVh = mk_desc(sb + SM_VT + kb * 8192);
                uint64_t dVl = mk_desc(sb + SM_VT + 16384 + kb * 8192);
#pragma unroll
                for (int ks = 0; ks < 4; ks++) {
                    uint32_t en0 = (kt == 0 && kb == 0 && ks == 0) ? 0u : 1u;
                    mma_f16_ss(tmem + 128, dPh + 2 * ks, dVh + 2 * ks, IDESC_O, en0);
                    mma_f16_ss(tmem + 128, dPl + 2 * ks, dVh + 2 * ks, IDESC_O, 1u);
                    mma_f16_ss(tmem + 128, dPh + 2 * ks, dVl + 2 * ks, IDESC_O, 1u);
                }
            }
            tc_commit(sb + 16);
        }
    }
    mbar_wait(sb + 16, (uint32_t)(oph & 1)); oph++;
    TC_FENCE_AFTER();

    float* lred = (float*)(sm + SM_P);
    lred[tid] = lpart;
    __syncthreads();
    if (wid < 4) {
        uint32_t o0[32], o1[32];
        TC_LD_X32(o0, tmem + 128);
        TC_LD_X32(o1, tmem + 160);
        TC_WAIT_LD();
        TC_FENCE_BEFORE();
        int r = wid * 32 + lane;
        float inv = 1.f / (lred[r] + lred[r + 128]);
        int b = bh >> 4, h = bh & 15;
        int s = qt * 128 + r;
        size_t base = ((size_t)(b * SS + s)) * DD + h * 64;
        uint32_t* ph = (uint32_t*)(outh + base);
        uint32_t* pl = (uint32_t*)(outl + base);
#pragma unroll
        for (int m = 0; m < 32; m++) {
            int c0 = 2 * m, c1 = 2 * m + 1;
            float v0 = __uint_as_float(c0 < 32 ? o0[c0] : o1[c0 - 32]) * inv;
            float v1 = __uint_as_float(c1 < 32 ? o0[c1] : o1[c1 - 32]) * inv;
            bf16 h0 = __float2bfloat16(v0), h1 = __float2bfloat16(v1);
            ph[m] = ((uint32_t)__bfloat16_as_ushort(h1) << 16) | __bfloat16_as_ushort(h0);
            pl[m] = pack_bf2(v0 - __bfloat162float(h0), v1 - __bfloat162float(h1));
        }
    }
    __syncthreads();
    if (wid == 0) { TC_DEALLOC(tmem, 256); }

#else
    // ---- SIMT fallback: two 64-row halves per CTA ----
    float* smf  = (float*)sm;
    float* Qs   = smf;
    float* Ks   = Qs + 64 * 65;
    float* Vs   = Ks + 64 * 65;
    float* Ps   = Vs + 64 * 65;
    float* mrow = Ps + 64 * 65;
    float* lrow = mrow + 64;
    float* arow = lrow + 64;
    int tx = tid & 15, ty = tid >> 4;
    const float scale = 0.125f;
    int b = bh >> 4, h = bh & 15;

    for (int h2 = 0; h2 < 2; h2++) {
        int qt64 = qt * 2 + h2;
        __syncthreads();
        for (int i = tid; i < 64 * 64; i += 256) {
            int r = i >> 6, d = i & 63;
            size_t o = ((size_t)bh * SS + qt64 * 64 + r) * DH + d;
            Qs[r * 65 + d] = (__bfloat162float(g_qkvh[0][o]) + __bfloat162float(g_qkvl[0][o])) * scale;
        }
        if (tid < 64) { mrow[tid] = -1e30f; lrow[tid] = 0.f; }
        float acc[4][4];
#pragma unroll
        for (int i = 0; i < 4; i++)
#pragma unroll
            for (int j = 0; j < 4; j++) acc[i][j] = 0.f;
        __syncthreads();

        for (int kt = 0; kt < SS / 64; kt++) {
            for (int i = tid; i < 64 * 64; i += 256) {
                int r = i >> 6, d = i & 63;
                size_t o = ((size_t)bh * SS + kt * 64 + r) * DH + d;
                Ks[r * 65 + d] = __bfloat162float(g_qkvh[1][o]) + __bfloat162float(g_qkvl[1][o]);
                Vs[r * 65 + d] = __bfloat162float(g_qkvh[2][o]) + __bfloat162float(g_qkvl[2][o]);
            }
            __syncthreads();
            float sv[4][4];
#pragma unroll
            for (int i = 0; i < 4; i++)
#pragma unroll
                for (int j = 0; j < 4; j++) sv[i][j] = 0.f;
            for (int d = 0; d < 64; d++) {
                float ar[4], br[4];
#pragma unroll
                for (int i = 0; i < 4; i++) ar[i] = Qs[(ty * 4 + i) * 65 + d];
#pragma unroll
                for (int j = 0; j < 4; j++) br[j] = Ks[(tx * 4 + j) * 65 + d];
#pragma unroll
                for (int i = 0; i < 4; i++)
#pragma unroll
                    for (int j = 0; j < 4; j++) sv[i][j] = fmaf(ar[i], br[j], sv[i][j]);
            }
#pragma unroll
            for (int i = 0; i < 4; i++)
#pragma unroll
                for (int j = 0; j < 4; j++)
                    Ps[(ty * 4 + i) * 65 + tx * 4 + j] = sv[i][j];
            __syncthreads();
            if (tid < 64) {
                int rr = tid;
                float m = mrow[rr], mx = m;
                for (int c = 0; c < 64; c++) mx = fmaxf(mx, Ps[rr * 65 + c]);
                float a = expf(m - mx), sum = 0.f;
                for (int c = 0; c < 64; c++) {
                    float p = expf(Ps[rr * 65 + c] - mx);
                    Ps[rr * 65 + c] = p; sum += p;
                }
                lrow[rr] = lrow[rr] * a + sum; mrow[rr] = mx; arow[rr] = a;
            }
            __syncthreads();
#pragma unroll
            for (int i = 0; i < 4; i++) {
                float a = arow[ty * 4 + i];
#pragma unroll
                for (int j = 0; j < 4; j++) acc[i][j] *= a;
            }
            for (int kk = 0; kk < 64; kk++) {
                float pr[4], vr[4];
#pragma unroll
                for (int i = 0; i < 4; i++) pr[i] = Ps[(ty * 4 + i) * 65 + kk];
#pragma unroll
                for (int j = 0; j < 4; j++) vr[j] = Vs[kk * 65 + tx * 4 + j];
#pragma unroll
                for (int i = 0; i < 4; i++)
#pragma unroll
                    for (int j = 0; j < 4; j++) acc[i][j] = fmaf(pr[i], vr[j], acc[i][j]);
            }
            __syncthreads();
        }
#pragma unroll
        for (int i = 0; i < 4; i++) {
            int rr = ty * 4 + i;
            float inv = 1.f / lrow[rr];
            int s = qt64 * 64 + rr;
#pragma unroll
            for (int j = 0; j < 4; j++) {
                int d = tx * 4 + j;
                size_t idx = ((size_t)(b * SS + s)) * DD + h * 64 + d;
                float val = acc[i][j] * inv;
                bf16 hh = __float2bfloat16(val);
                outh[idx] = hh;
                outl[idx] = __float2bfloat16(val - __bfloat162float(hh));
            }
        }
    }
#endif
#endif // __CUDA_ARCH__
}

// ---------------- router ----------------
__global__ void zero_cnt_kernel() {
    if (threadIdx.x < NE) g_cnt[threadIdx.x] = 0;
}

__global__ void router_kernel(const float* __restrict__ xn2, const float* __restrict__ wr)
{
    int t = blockIdx.x;
    int lane = threadIdx.x;
    float p[NE];
#pragma unroll
    for (int e = 0; e < NE; e++) p[e] = 0.f;
    const float* xr = xn2 + (size_t)t * DD;
    for (int d = lane; d < DD; d += 32) {
        float xv = xr[d];
        const float* wrow = wr + (size_t)d * NE;
#pragma unroll
        for (int e = 0; e < NE; e++) p[e] = fmaf(xv, wrow[e], p[e]);
    }
#pragma unroll
    for (int e = 0; e < NE; e++) {
        for (int o = 16; o > 0; o >>= 1) p[e] += __shfl_xor_sync(0xffffffffu, p[e], o);
    }
    if (lane == 0) {
        float m = p[0];
#pragma unroll
        for (int e = 1; e < NE; e++) m = fmaxf(m, p[e]);
        float pr[NE];
        float sum = 0.f;
#pragma unroll
        for (int e = 0; e < NE; e++) { pr[e] = expf(p[e] - m); sum += pr[e]; }
        float inv = 1.f / sum;
#pragma unroll
        for (int e = 0; e < NE; e++) pr[e] *= inv;
        g_zz[t] = m + logf(sum);
#pragma unroll
        for (int e = 0; e < NE; e++) g_probs[t * NE + e] = pr[e];
        int i0 = 0; float v0 = pr[0];
#pragma unroll
        for (int e = 1; e < NE; e++) if (pr[e] > v0) { v0 = pr[e]; i0 = e; }
        int i1 = -1; float v1 = -1.f;
#pragma unroll
        for (int e = 0; e < NE; e++) { if (e == i0) continue; if (pr[e] > v1) { v1 = pr[e]; i1 = e; } }
        float wsum = v0 + v1;
        float w0 = v0 / wsum, w1 = v1 / wsum;
        int r0 = atomicAdd(&g_cnt[i0], 1); g_rowlist[i0 * TT + r0] = t;
        int r1 = atomicAdd(&g_cnt[i1], 1); g_rowlist[i1 * TT + r1] = t;
        g_slot_e[2 * t]     = i0; g_slot_r[2 * t]     = r0; g_slot_w[2 * t]     = w0;
        g_slot_e[2 * t + 1] = i1; g_slot_r[2 * t + 1] = r1; g_slot_w[2 * t + 1] = w1;
    }
}

// ---------------- loss (deterministic tree reduction) ----------------
__global__ void loss_kernel(float* __restrict__ out, int out_size)
{
    int tid = threadIdx.x;
    __shared__ float red[256];
    __shared__ float sumsp[NE];
    __shared__ float sumz;
    float accp[NE];
#pragma unroll
    for (int e = 0; e < NE; e++) accp[e] = 0.f;
    float accz = 0.f;
    for (int t = tid; t < TT; t += 256) {
        float z = g_zz[t];
        accz += z * z;
#pragma unroll
        for (int e = 0; e < NE; e++) accp[e] += g_probs[t * NE + e];
    }
    red[tid] = accz; __syncthreads();
    for (int o = 128; o > 0; o >>= 1) { if (tid < o) red[tid] += red[tid + o]; __syncthreads(); }
    if (tid == 0) sumz = red[0];
    __syncthreads();
    for (int e = 0; e < NE; e++) {
        red[tid] = accp[e]; __syncthreads();
        for (int o = 128; o > 0; o >>= 1) { if (tid < o) red[tid] += red[tid + o]; __syncthreads(); }
        if (tid == 0) sumsp[e] = red[0];
        __syncthreads();
    }
    if (tid == 0) {
        float aux = 0.f;
        for (int e = 0; e < NE; e++) {
            float ft = (float)g_cnt[e] / (float)TT;
            float fp = sumsp[e] / (float)TT;
            aux += ft * fp;
        }
        aux *= (float)NE / 2.f;
        float loss = aux + 0.001f * (sumz / (float)TT);
        for (int i = NMAIN; i < out_size; i++) out[i] = loss;
    }
}

// ---------------- combine ----------------
__global__ void combine_kernel(float* __restrict__ out)
{
    int idx = blockIdx.x * 256 + threadIdx.x;
    if (idx >= NMAIN) return;
    int t = idx >> 10;
    int d = idx & 1023;
    int e0 = g_slot_e[2 * t], r0 = g_slot_r[2 * t];
    int e1 = g_slot_e[2 * t + 1], r1 = g_slot_r[2 * t + 1];
    float w0 = g_slot_w[2 * t], w1 = g_slot_w[2 * t + 1];
    float y = g_x2[idx]
            + w0 * g_Y[((size_t)e0 * TT + r0) * DD + d]
            + w1 * g_Y[((size_t)e1 * TT + r1) * DD + d];
    out[idx] = y;
}

// ---------------- launch ----------------
extern "C" void kernel_launch(void* const* d_in, const int* in_sizes, int n_in,
                              void* d_out, int out_size)
{
    const float* x   = (const float*)d_in[0];
    const float* ln1 = (const float*)d_in[1];
    const float* ln2 = (const float*)d_in[2];
    const float* wq  = (const float*)d_in[3];
    const float* wk  = (const float*)d_in[4];
    const float* wv  = (const float*)d_in[5];
    const float* wo  = (const float*)d_in[6];
    const float* wr  = (const float*)d_in[7];
    const float* w1  = (const float*)d_in[8];
    const float* w2  = (const float*)d_in[9];
    float* out = (float*)d_out;

    cudaFuncSetAttribute(tc_attn, cudaFuncAttributeMaxDynamicSharedMemorySize, ATT_SMEM);
    cudaFuncSetAttribute(tc_gemm<GM_QKV>,  cudaFuncAttributeMaxDynamicSharedMemorySize, G_SMEM);
    cudaFuncSetAttribute(tc_gemm<GM_RES>,  cudaFuncAttributeMaxDynamicSharedMemorySize, G_SMEM);
    cudaFuncSetAttribute(tc_gemm<GM_MOE1>, cudaFuncAttributeMaxDynamicSharedMemorySize, G_SMEM);
    cudaFuncSetAttribute(tc_gemm<GM_MOE2>, cudaFuncAttributeMaxDynamicSharedMemorySize, G_SMEM);

    bf16 *p_xnh, *p_xnl, *p_xn2h, *p_xn2l, *p_ctxh, *p_ctxl;
    bf16 *p_wpth, *p_wptl, *p_w1th, *p_w1tl, *p_w2th, *p_w2tl, *p_Hh, *p_Hl;
    float *p_xn2, *p_x2, *p_Y;
    cudaGetSymbolAddress((void**)&p_xnh,  g_xnh);
    cudaGetSymbolAddress((void**)&p_xnl,  g_xnl);
    cudaGetSymbolAddress((void**)&p_xn2,  g_xn2);
    cudaGetSymbolAddress((void**)&p_xn2h, g_xn2h);
    cudaGetSymbolAddress((void**)&p_xn2l, g_xn2l);
    cudaGetSymbolAddress((void**)&p_ctxh, g_ctxh);
    cudaGetSymbolAddress((void**)&p_ctxl, g_ctxl);
    cudaGetSymbolAddress((void**)&p_x2,   g_x2);
    cudaGetSymbolAddress((void**)&p_wpth, g_wpth);
    cudaGetSymbolAddress((void**)&p_wptl, g_wptl);
    cudaGetSymbolAddress((void**)&p_w1th, g_w1th);
    cudaGetSymbolAddress((void**)&p_w1tl, g_w1tl);
    cudaGetSymbolAddress((void**)&p_w2th, g_w2th);
    cudaGetSymbolAddress((void**)&p_w2tl, g_w2tl);
    cudaGetSymbolAddress((void**)&p_Hh,   g_Hh);
    cudaGetSymbolAddress((void**)&p_Hl,   g_Hl);
    cudaGetSymbolAddress((void**)&p_Y,    g_Y);

    // launches 0-3: attention-path weight converts
    dim3 bt(256);
    wt_convert_kernel<<<dim3(DD/64, DD/64, 1), bt>>>(wq, p_wpth,           p_wptl,           DD, DD);
    wt_convert_kernel<<<dim3(DD/64, DD/64, 1), bt>>>(wk, p_wpth + DD*DD,   p_wptl + DD*DD,   DD, DD);
    wt_convert_kernel<<<dim3(DD/64, DD/64, 1), bt>>>(wv, p_wpth + 2*DD*DD, p_wptl + 2*DD*DD, DD, DD);
    wt_convert_kernel<<<dim3(DD/64, DD/64, 1), bt>>>(wo, p_wpth + 3*DD*DD, p_wptl + 3*DD*DD, DD, DD);

    // launch 4: rmsnorm 1
    rmsnorm_kernel<<<TT, 256>>>(x, ln1, nullptr, p_xnh, p_xnl);

    // launch 5 (profiled by ncu -s 5): QKV projections
    tc_gemm<GM_QKV><<<dim3(DD/256, TT/128, 3), 256, G_SMEM>>>(
        p_xnh, p_xnl, p_wpth, p_wptl, nullptr, nullptr, nullptr, nullptr, TT, DD, DD);

    // MoE weight converts (any time before MOE1)
    wt_convert_kernel<<<dim3(FF/64, DD/64, NE), bt>>>(w1, p_w1th, p_w1tl, DD, FF);
    wt_convert_kernel<<<dim3(DD/64, FF/64, NE), bt>>>(w2, p_w2th, p_w2tl, FF, DD);

    // attention (tcgen05, cp.async KV prefetch) -> ctx bf16 split
    tc_attn<<<dim3(BB * NH, SS / 128), 256, ATT_SMEM>>>(p_ctxh, p_ctxl);

    // output projection + residual
    tc_gemm<GM_RES><<<dim3(DD/256, TT/128, 1), 256, G_SMEM>>>(
        p_ctxh, p_ctxl, p_wpth + 3*DD*DD, p_wptl + 3*DD*DD, p_x2, x, nullptr, nullptr, TT, DD, DD);

    // rmsnorm 2
    rmsnorm_kernel<<<TT, 256>>>(p_x2, ln2, p_xn2, p_xn2h, p_xn2l);

    // router
    zero_cnt_kernel<<<1, 32>>>();
    router_kernel<<<TT, 32>>>(p_xn2, wr);

    // loss scalar -> out[NMAIN..]
    loss_kernel<<<1, 256>>>(out, out_size);

    // MoE expert GEMMs (grouped; tiles beyond per-expert count early-exit)
    tc_gemm<GM_MOE1><<<dim3(FF/256, TT/128, NE), 256, G_SMEM>>>(
        p_xn2h, p_xn2l, p_w1th, p_w1tl, nullptr, nullptr, p_Hh, p_Hl, TT, FF, DD);
    tc_gemm<GM_MOE2><<<dim3(DD/256, TT/128, NE), 256, G_SMEM>>>(
        p_Hh, p_Hl, p_w2th, p_w2tl, p_Y, nullptr, nullptr, nullptr, TT, DD, FF);

    // combine + residual -> out
    combine_kernel<<<(NMAIN + 255) / 256, 256>>>(out);
}

// round 9
// speedup vs baseline: 2.1045x; 2.1045x over previous
#include <cuda_runtime.h>
#include <cuda_fp16.h>
#include <math.h>
#include <stdint.h>

#define BB 2
#define SS 2048
#define DD 1024
#define NH 16
#define DH 64
#define NE 8
#define FF 4096
#define TT (BB*SS)
#define NMAIN (TT*DD)
#define LO_INV 0.0009765625f

typedef __half fp16;

__device__ fp16  g_xn[TT*DD];
__device__ float g_xn2f[TT*DD];
__device__ fp16  g_xn2[TT*DD];
__device__ fp16  g_qkv[3][(size_t)TT*DD];
__device__ fp16  g_ctx[TT*DD];
__device__ float g_x2[TT*DD];
__device__ fp16  g_wpth[4*DD*DD], g_wptl[4*DD*DD];
__device__ fp16  g_w1th[(size_t)NE*DD*FF], g_w1tl[(size_t)NE*DD*FF];
__device__ fp16  g_w2th[(size_t)NE*DD*FF], g_w2tl[(size_t)NE*DD*FF];
__device__ fp16  g_H[(size_t)NE*TT*FF];
__device__ float g_Y[(size_t)NE*TT*DD];
__device__ float g_probs[TT*NE];
__device__ float g_zz[TT];
__device__ int   g_cnt[NE];
__device__ int   g_rowlist[NE*TT];
__device__ int   g_slot_e[2*TT];
__device__ int   g_slot_r[2*TT];
__device__ float g_slot_w[2*TT];

__device__ __forceinline__ uint32_t smem_u32(const void* p) {
    uint32_t a;
    asm("{ .reg .u64 t; cvta.to.shared.u64 t, %1; cvt.u32.u64 %0, t; }" : "=r"(a) : "l"(p));
    return a;
}
__device__ __forceinline__ uint32_t elect1() {
    uint32_t p;
    asm volatile("{\n.reg .pred p;\nelect.sync _|p, 0xFFFFFFFF;\nselp.b32 %0, 1, 0, p;\n}" : "=r"(p));
    return p;
}
__device__ __forceinline__ void mbar_init(uint32_t a, uint32_t n) {
    asm volatile("mbarrier.init.shared.b64 [%0], %1;" :: "r"(a), "r"(n) : "memory");
}
__device__ __forceinline__ void mbar_wait(uint32_t a, uint32_t par) {
    asm volatile(
        "{\n.reg .pred P;\nLW%=:\n"
        "mbarrier.try_wait.parity.acquire.cta.shared::cta.b64 P, [%0], %1, 0x989680;\n"
        "@P bra LD%=;\nbra LW%=;\nLD%=:\n}" :: "r"(a), "r"(par) : "memory");
}
__device__ __forceinline__ uint64_t mk_desc(uint32_t addr) {
    return ((uint64_t)2 << 61) | ((uint64_t)1 << 46) | ((uint64_t)64 << 32)
         | ((uint64_t)1 << 16) | ((addr >> 4) & 0x3FFF);
}
__device__ __forceinline__ void tc_commit(uint32_t mbar) {
#if defined(__CUDA_ARCH_FEAT_SM103_ALL)
    asm volatile("tcgen05.commit.cta_group::1.mbarrier::arrive::one.shared::cluster.b64 [%0];"
                 :: "r"(mbar) : "memory");
#endif
}
__device__ __forceinline__ void mma_f16_ss(uint32_t d, uint64_t ad, uint64_t bd,
                                           uint32_t idesc, uint32_t en) {
#if defined(__CUDA_ARCH_FEAT_SM103_ALL)
    asm volatile(
        "{\n.reg .pred p;\nsetp.ne.u32 p, %4, 0;\n"
        "tcgen05.mma.cta_group::1.kind::f16 [%0], %1, %2, %3, {%5, %5, %5, %5}, p;\n}"
        :: "r"(d), "l"(ad), "l"(bd), "r"(idesc), "r"(en), "r"(0u) : "memory");
#endif
}

#if defined(__CUDA_ARCH_FEAT_SM103_ALL)
#define TC_ALLOC(sbaddr, n) \
    asm volatile("tcgen05.alloc.cta_group::1.sync.aligned.shared::cta.b32 [%0], %1;" \
                 :: "r"(sbaddr), "r"((uint32_t)(n)) : "memory")
#define TC_RELINQ() asm volatile("tcgen05.relinquish_alloc_permit.cta_group::1.sync.aligned;")
#define TC_DEALLOC(t, n) \
    asm volatile("tcgen05.dealloc.cta_group::1.sync.aligned.b32 %0, %1;" :: "r"(t), "r"((uint32_t)(n)))
#define TC_FENCE_AFTER()  asm volatile("tcgen05.fence::after_thread_sync;" ::: "memory")
#define TC_FENCE_BEFORE() asm volatile("tcgen05.fence::before_thread_sync;" ::: "memory")
#define TC_WAIT_LD()      asm volatile("tcgen05.wait::ld.sync.aligned;" ::: "memory")
#define TC_LD_X32(r, ta) \
    asm volatile( \
        "tcgen05.ld.sync.aligned.32x32b.x32.b32 " \
        "{%0, %1, %2, %3, %4, %5, %6, %7, %8, %9, %10, %11, %12, %13, %14, %15, " \
        " %16, %17, %18, %19, %20, %21, %22, %23, %24, %25, %26, %27, %28, %29, %30, %31}, [%32];" \
        : "=r"((r)[0]),  "=r"((r)[1]),  "=r"((r)[2]),  "=r"((r)[3]), \
          "=r"((r)[4]),  "=r"((r)[5]),  "=r"((r)[6]),  "=r"((r)[7]), \
          "=r"((r)[8]),  "=r"((r)[9]),  "=r"((r)[10]), "=r"((r)[11]), \
          "=r"((r)[12]), "=r"((r)[13]), "=r"((r)[14]), "=r"((r)[15]), \
          "=r"((r)[16]), "=r"((r)[17]), "=r"((r)[18]), "=r"((r)[19]), \
          "=r"((r)[20]), "=r"((r)[21]), "=r"((r)[22]), "=r"((r)[23]), \
          "=r"((r)[24]), "=r"((r)[25]), "=r"((r)[26]), "=r"((r)[27]), \
          "=r"((r)[28]), "=r"((r)[29]), "=r"((r)[30]), "=r"((r)[31]) \
        : "r"(ta))
#endif

__device__ __forceinline__ float gelu_tanh(float x) {
    float x3 = x * x * x;
    return 0.5f * x * (1.f + tanhf(0.7978845608028654f * (x + 0.044715f * x3)));
}
__device__ __forceinline__ uint32_t pack_h2(float a, float b) {
    __half2 h = __floats2half2_rn(a, b);
    return *(uint32_t*)&h;
}

// ---------------- rmsnorm (vectorized; optional fp32 out + fp16 out) --------
__global__ void rmsnorm_kernel(const float* __restrict__ x, const float* __restrict__ w,
                               float* __restrict__ yf, fp16* __restrict__ yh)
{
    int row = blockIdx.x, tid = threadIdx.x;
    const float* xr = x + (size_t)row * DD;
    int d4 = tid * 4;
    float4 xv = *(const float4*)(xr + d4);
    float s = xv.x * xv.x + xv.y * xv.y + xv.z * xv.z + xv.w * xv.w;
    __shared__ float red[8];
    for (int o = 16; o > 0; o >>= 1) s += __shfl_xor_sync(0xffffffffu, s, o);
    if ((tid & 31) == 0) red[tid >> 5] = s;
    __syncthreads();
    float tot = 0.f;
#pragma unroll
    for (int i = 0; i < 8; i++) tot += red[i];
    float inv = rsqrtf(tot / (float)DD + 1e-6f);
    float4 wv = *(const float4*)(w + d4);
    float v0 = xv.x * inv * wv.x, v1 = xv.y * inv * wv.y;
    float v2 = xv.z * inv * wv.z, v3 = xv.w * inv * wv.w;
    if (yf) *(float4*)(yf + (size_t)row * DD + d4) = make_float4(v0, v1, v2, v3);
    uint2 p; p.x = pack_h2(v0, v1); p.y = pack_h2(v2, v3);
    *(uint2*)(yh + (size_t)row * DD + d4) = p;
}

// ---------------- weight transpose + fp16 split (hi + lo*1024) -------------
__global__ void wt_convert_kernel(const float* __restrict__ W,
                                  fp16* __restrict__ Th, fp16* __restrict__ Tl,
                                  int K, int N)
{
    __shared__ float tile[64][68];
    size_t zoff = (size_t)blockIdx.z * K * N;
    int n0 = blockIdx.x * 64, k0 = blockIdx.y * 64;
    int tx = threadIdx.x & 15, ty = threadIdx.x >> 4;
#pragma unroll
    for (int i = 0; i < 4; i++) {
        int r = ty + 16 * i;
        *(float4*)&tile[r][tx * 4] = *(const float4*)(W + zoff + (size_t)(k0 + r) * N + n0 + tx * 4);
    }
    __syncthreads();
#pragma unroll
    for (int i = 0; i < 4; i++) {
        int n = ty + 16 * i, kk = tx * 4;
        float v[4], l[4];
        uint32_t hp[2];
#pragma unroll
        for (int j = 0; j < 4; j++) v[j] = tile[kk + j][n];
        fp16 h0 = __float2half_rn(v[0]), h1 = __float2half_rn(v[1]);
        fp16 h2 = __float2half_rn(v[2]), h3 = __float2half_rn(v[3]);
        l[0] = (v[0] - __half2float(h0)) * 1024.f;
        l[1] = (v[1] - __half2float(h1)) * 1024.f;
        l[2] = (v[2] - __half2float(h2)) * 1024.f;
        l[3] = (v[3] - __half2float(h3)) * 1024.f;
        __half2 a = __halves2half2(h0, h1); hp[0] = *(uint32_t*)&a;
        __half2 b = __halves2half2(h2, h3); hp[1] = *(uint32_t*)&b;
        size_t idx = zoff + (size_t)(n0 + n) * K + k0 + kk;
        *(uint2*)(Th + idx) = make_uint2(hp[0], hp[1]);
        *(uint2*)(Tl + idx) = make_uint2(pack_h2(l[0], l[1]), pack_h2(l[2], l[3]));
    }
}

#define GM_QKV  1
#define GM_RES  2
#define GM_MOE1 3
#define GM_MOE2 4
#define BUF_BYTES 81920
#define G_SMEM  (1024 + 2 * BUF_BYTES)   // 164864

// ---------------- tcgen05 GEMM: C[128x256], fp16, dual accumulator ---------
template<int MODE>
__global__ void __launch_bounds__(256, 1)
tc_gemm(const fp16* __restrict__ A,
        const fp16* __restrict__ Bh0, const fp16* __restrict__ Bl0,
        float* __restrict__ Cf, const float* __restrict__ Res,
        fp16* __restrict__ Ch, int M, int N, int K)
{
#if defined(__CUDA_ARCH__)
    extern __shared__ char sm[];
    int tid = threadIdx.x;
    int e  = blockIdx.z;
    int m0 = blockIdx.y * 128, n0 = blockIdx.x * 256;
    int Me = M;
    const fp16* Bh = Bh0;
    const fp16* Bl = Bl0;
    if (MODE == GM_MOE1 || MODE == GM_MOE2) {
        Me = g_cnt[e];
        if (m0 >= Me) return;
        Bh += (size_t)e * (size_t)K * N; Bl += (size_t)e * (size_t)K * N;
    } else if (MODE == GM_QKV) {
        Bh += (size_t)e * (size_t)K * N; Bl += (size_t)e * (size_t)K * N;
    }

#if defined(__CUDA_ARCH_FEAT_SM103_ALL)
    uint32_t sb = smem_u32(sm);
    int wid = tid >> 5, lid = tid & 31;
    int nk = K / 64;

    auto issue_fill = [&](int kc, int bufi) {
        uint32_t tb = sb + 1024 + (uint32_t)bufi * BUF_BYTES;
        for (int task = tid; task < 384; task += 256) {
            if (task < 128) {
                int gr = m0 + task;
                bool val = gr < Me;
                size_t ri = 0;
                if (val) {
                    if (MODE == GM_MOE1)      ri = (size_t)g_rowlist[e * TT + gr];
                    else if (MODE == GM_MOE2) ri = (size_t)e * TT + gr;
                    else                      ri = (size_t)gr;
                }
                const char* src = (const char*)(A + ri * (size_t)K + kc * 64);
                uint32_t sz = val ? 16u : 0u;
#pragma unroll
                for (int j = 0; j < 8; j++) {
                    uint32_t off = (uint32_t)task * 128u + j * 16u;
                    uint32_t swz = off ^ ((off >> 3) & 0x70);
                    asm volatile("cp.async.cg.shared.global [%0], [%1], 16, %2;"
                                 :: "r"(tb + swz), "l"(src + j * 16), "r"(sz) : "memory");
                }
            } else {
                int row = task - 128;
                const char* sh = (const char*)(Bh + (size_t)(n0 + row) * K + kc * 64);
                const char* sl = (const char*)(Bl + (size_t)(n0 + row) * K + kc * 64);
#pragma unroll
                for (int j = 0; j < 8; j++) {
                    uint32_t off = (uint32_t)row * 128u + j * 16u;
                    uint32_t swz = off ^ ((off >> 3) & 0x70);
                    asm volatile("cp.async.cg.shared.global [%0], [%1], 16;"
                                 :: "r"(tb + 16384 + swz), "l"(sh + j * 16) : "memory");
                    asm volatile("cp.async.cg.shared.global [%0], [%1], 16;"
                                 :: "r"(tb + 49152 + swz), "l"(sl + j * 16) : "memory");
                }
            }
        }
        asm volatile("cp.async.commit_group;" ::: "memory");
    };

    issue_fill(0, 0);
    if (nk > 1) issue_fill(1, 1);

    if (wid == 0) { TC_ALLOC(sb, 512); TC_RELINQ(); }
    if (tid == 0) { mbar_init(sb + 8, 1); mbar_init(sb + 16, 1); }
    __syncthreads();
    uint32_t tmem;
    asm volatile("ld.shared.b32 %0, [%1];" : "=r"(tmem) : "r"(sb));

    const uint32_t IDESC = (1u << 4) | (32u << 17) | (8u << 24);   // f16 in, f32 acc, N=256, M=128
    int ph0 = 0, ph1 = 0;
    for (int kc = 0; kc < nk; kc++) {
        int b = kc & 1;
        if (kc >= 1 && kc + 1 < nk) {
            int nb = 1 - b;
            if (nb == 0) { mbar_wait(sb + 8,  (uint32_t)(ph0 & 1)); ph0++; }
            else         { mbar_wait(sb + 16, (uint32_t)(ph1 & 1)); ph1++; }
            issue_fill(kc + 1, nb);
        }
        if (kc + 1 < nk) asm volatile("cp.async.wait_group 1;" ::: "memory");
        else             asm volatile("cp.async.wait_group 0;" ::: "memory");
        asm volatile("fence.proxy.async.shared::cta;" ::: "memory");
        __syncthreads();
        if (wid == 0 && elect1()) {
            uint32_t tb = sb + 1024 + (uint32_t)b * BUF_BYTES;
            uint64_t dA  = mk_desc(tb);
            uint64_t dBh = mk_desc(tb + 16384);
            uint64_t dBl = mk_desc(tb + 49152);
#pragma unroll
            for (int s = 0; s < 4; s++) {
                uint32_t en0 = (kc == 0 && s == 0) ? 0u : 1u;
                mma_f16_ss(tmem,       dA + 2 * s, dBh + 2 * s, IDESC, en0);
                mma_f16_ss(tmem + 256, dA + 2 * s, dBl + 2 * s, IDESC, en0);
            }
            tc_commit(sb + 8 + b * 8);
        }
    }
    {
        int lb = (nk - 1) & 1;
        if (lb == 0) mbar_wait(sb + 8,  (uint32_t)(ph0 & 1));
        else         mbar_wait(sb + 16, (uint32_t)(ph1 & 1));
    }
    TC_FENCE_AFTER();

    int rw = wid & 3, cw = wid >> 2;
    int rows_here = Me - m0; if (rows_here > 128) rows_here = 128;
    float* Cs = (float*)(sm + 1024);
#pragma unroll 1
    for (int p = 0; p < 2; p++) {
        uint32_t d0[32], d1[32], e0[32], e1[32];
        TC_LD_X32(d0, tmem + p * 128 + cw * 64);
        TC_LD_X32(d1, tmem + p * 128 + cw * 64 + 32);
        TC_LD_X32(e0, tmem + 256 + p * 128 + cw * 64);
        TC_LD_X32(e1, tmem + 256 + p * 128 + cw * 64 + 32);
        TC_WAIT_LD();
        TC_FENCE_BEFORE();
        __syncthreads();
        {
            int rr = rw * 32 + lid, cb = cw * 64;
#pragma unroll
            for (int j = 0; j < 32; j++) {
                Cs[rr * 129 + cb + j]      = __uint_as_float(d0[j]) + __uint_as_float(e0[j]) * LO_INV;
                Cs[rr * 129 + cb + 32 + j] = __uint_as_float(d1[j]) + __uint_as_float(e1[j]) * LO_INV;
            }
        }
        __syncthreads();
#pragma unroll 4
        for (int it = 0; it < 16; it++) {
            int idx4 = (it * 256 + tid) * 4;
            int rr = idx4 >> 7, cc = idx4 & 127;
            if (rr >= rows_here) continue;
            float v0 = Cs[rr * 129 + cc + 0], v1 = Cs[rr * 129 + cc + 1];
            float v2 = Cs[rr * 129 + cc + 2], v3 = Cs[rr * 129 + cc + 3];
            int colb = n0 + p * 128 + cc;
            if (MODE == GM_RES) {
                size_t o = (size_t)(m0 + rr) * N + colb;
                float4 rs = *(const float4*)(Res + o);
                *(float4*)(Cf + o) = make_float4(v0 + rs.x, v1 + rs.y, v2 + rs.z, v3 + rs.w);
            } else if (MODE == GM_MOE2) {
                size_t o = ((size_t)e * TT + m0 + rr) * N + colb;
                *(float4*)(Cf + o) = make_float4(v0, v1, v2, v3);
            } else if (MODE == GM_MOE1) {
                size_t o = ((size_t)e * TT + m0 + rr) * N + colb;
                uint2 ph;
                ph.x = pack_h2(gelu_tanh(v0), gelu_tanh(v1));
                ph.y = pack_h2(gelu_tanh(v2), gelu_tanh(v3));
                *(uint2*)(Ch + o) = ph;
            } else {
                int row = m0 + rr;
                int b2 = row >> 11, s5 = row & (SS - 1);
                int h = colb >> 6, dh = colb & 63;
                size_t o = (((size_t)(b2 * NH + h)) * SS + s5) * DH + dh;
                uint2 ph; ph.x = pack_h2(v0, v1); ph.y = pack_h2(v2, v3);
                *(uint2*)(g_qkv[e] + o) = ph;
            }
        }
        __syncthreads();
    }
    if (wid == 0) { TC_DEALLOC(tmem, 512); }

#else
    // compact SIMT fallback (never runs when sm_103a SASS is loaded)
    for (int i = tid; i < 128 * 256; i += 256) {
        int rr = i >> 8, cc = i & 255;
        int row = m0 + rr;
        if (row >= Me) continue;
        size_t ri;
        if (MODE == GM_MOE1)      ri = (size_t)g_rowlist[e * TT + row];
        else if (MODE == GM_MOE2) ri = (size_t)e * TT + row;
        else                      ri = (size_t)row;
        float acc = 0.f;
        const fp16* ar = A + ri * (size_t)K;
        const fp16* bh = Bh + (size_t)(n0 + cc) * K;
        const fp16* bl = Bl + (size_t)(n0 + cc) * K;
        for (int k = 0; k < K; k++)
            acc += __half2float(ar[k]) * (__half2float(bh[k]) + __half2float(bl[k]) * LO_INV);
        if (MODE == GM_RES) { size_t o = (size_t)row * N + n0 + cc; Cf[o] = acc + Res[o]; }
        else if (MODE == GM_MOE2) Cf[((size_t)e * TT + row) * N + n0 + cc] = acc;
        else if (MODE == GM_MOE1) Ch[((size_t)e * TT + row) * N + n0 + cc] = __float2half_rn(gelu_tanh(acc));
        else {
            int col = n0 + cc, b2 = row >> 11, s5 = row & (SS - 1);
            g_qkv[e][(((size_t)(b2 * NH + (col >> 6))) * SS + s5) * DH + (col & 63)] = __float2half_rn(acc);
        }
    }
#endif
#endif
}

// ---------------- tcgen05 flash attention, fp16 single-term, 2 CTA/SM ------
#define SM_Q   1024
#define SM_K   17408
#define SM_VST 33792
#define SM_VT  50176
#define SM_P   66560
#define ATT_SMEM 100352

__global__ void __launch_bounds__(256, 2)
tc_attn(fp16* __restrict__ outh)
{
#if defined(__CUDA_ARCH__)
    extern __shared__ char sm[];
    int tid = threadIdx.x;
    int bh = blockIdx.x;
    int qt = blockIdx.y;

#if defined(__CUDA_ARCH_FEAT_SM103_ALL)
    uint32_t sb = smem_u32(sm);
    int wid = tid >> 5, lane = tid & 31;

    auto fill_kv = [&](int kt) {
        int arr = tid >> 7, r = tid & 127;
        const fp16* src = (arr == 0 ? g_qkv[1] : g_qkv[2]);
        uint32_t dstb = (arr == 0 ? sb + SM_K : sb + SM_VST);
        const char* s4 = (const char*)(src + ((size_t)bh * SS + kt * 128 + r) * DH);
        if (arr == 0) {
#pragma unroll
            for (int j = 0; j < 8; j++) {
                uint32_t off = (uint32_t)r * 128u + j * 16u;
                uint32_t swz = off ^ ((off >> 3) & 0x70);
                asm volatile("cp.async.cg.shared.global [%0], [%1], 16;"
                             :: "r"(dstb + swz), "l"(s4 + j * 16) : "memory");
            }
        } else {
#pragma unroll
            for (int j = 0; j < 8; j++)
                asm volatile("cp.async.cg.shared.global [%0], [%1], 16;"
                             :: "r"(dstb + (uint32_t)r * 128u + j * 16u), "l"(s4 + j * 16) : "memory");
        }
        asm volatile("cp.async.commit_group;" ::: "memory");
    };

    fill_kv(0);

    if (wid == 0) { TC_ALLOC(sb, 256); TC_RELINQ(); }
    if (tid == 0) { mbar_init(sb + 8, 1); mbar_init(sb + 16, 1); }
    __syncthreads();
    uint32_t tmem;
    asm volatile("ld.shared.b32 %0, [%1];" : "=r"(tmem) : "r"(sb));

    // load Q tile fp16: 256 threads, half-row each
    {
        int r = tid & 127, j0 = (tid >> 7) * 4;
        const uint4* s4 = (const uint4*)(g_qkv[0] + ((size_t)bh * SS + qt * 128 + r) * DH);
#pragma unroll
        for (int j = 0; j < 4; j++) {
            uint32_t off = (uint32_t)r * 128u + (j0 + j) * 16u;
            uint32_t swz = off ^ ((off >> 3) & 0x70);
            *(uint4*)(sm + SM_Q + swz) = s4[j0 + j];
        }
    }

    const uint32_t IDESC_S = (1u << 4) | (16u << 17) | (8u << 24);
    const uint32_t IDESC_O = (1u << 4) | (8u << 17)  | (8u << 24);
    int sph = 0, oph = 0;
    float lpart = 0.f;
    const int NKT = SS / 128;

    for (int kt = 0; kt < NKT; kt++) {
        if (kt > 0) { mbar_wait(sb + 16, (uint32_t)(oph & 1)); oph++; }
        asm volatile("cp.async.wait_group 0;" ::: "memory");
        asm volatile("fence.proxy.async.shared::cta;" ::: "memory");
        __syncthreads();

        if (wid == 0 && elect1()) {
            uint64_t dQ = mk_desc(sb + SM_Q);
            uint64_t dK = mk_desc(sb + SM_K);
#pragma unroll
            for (int ks = 0; ks < 4; ks++)
                mma_f16_ss(tmem, dQ + 2 * ks, dK + 2 * ks, IDESC_S, ks == 0 ? 0u : 1u);
            tc_commit(sb + 8);
        }

        // transpose V (overlaps S MMA): VT kb = [64 d][64 s], SW128
        {
            int d = tid & 63, shb = (tid >> 6) & 1, mh = tid >> 7;
            const unsigned short* vs = (const unsigned short*)(sm + SM_VST);
            char* vt = sm + SM_VT + shb * 8192;
#pragma unroll
            for (int i = 0; i < 16; i++) {
                int m = mh * 16 + i;
                int s0 = shb * 64 + 2 * m;
                uint32_t u = (uint32_t)vs[s0 * 64 + d] | ((uint32_t)vs[(s0 + 1) * 64 + d] << 16);
                uint32_t off = (uint32_t)d * 128u + m * 4u;
                uint32_t swz = off ^ ((off >> 3) & 0x70);
                *(uint32_t*)(vt + swz) = u;
            }
        }
        asm volatile("fence.proxy.async.shared::cta;" ::: "memory");
        __syncthreads();

        mbar_wait(sb + 8, (uint32_t)(sph & 1)); sph++;
        TC_FENCE_AFTER();

        if (kt + 1 < NKT) fill_kv(kt + 1);

        // exp epilogue -> P fp16
        {
            int rw = wid & 3, cw = wid >> 2;
            uint32_t s0[32], s1[32];
            TC_LD_X32(s0, tmem + cw * 64);
            TC_LD_X32(s1, tmem + cw * 64 + 32);
            TC_WAIT_LD();
            TC_FENCE_BEFORE();
            int r = rw * 32 + lane;
            char* pb = sm + SM_P + cw * 16384;
#pragma unroll
            for (int m = 0; m < 32; m++) {
                int c0 = 2 * m, c1 = 2 * m + 1;
                float a = __uint_as_float(c0 < 32 ? s0[c0] : s1[c0 - 32]);
                float b = __uint_as_float(c1 < 32 ? s0[c1] : s1[c1 - 32]);
                float pa = __expf(a * 0.125f);
                float pbv = __expf(b * 0.125f);
                lpart += pa + pbv;
                uint32_t off = (uint32_t)r * 128u + m * 4u;
                uint32_t swz = off ^ ((off >> 3) & 0x70);
                *(uint32_t*)(pb + swz) = pack_h2(pa, pbv);
            }
        }
        asm volatile("fence.proxy.async.shared::cta;" ::: "memory");
        __syncthreads();

        if (wid == 0 && elect1()) {
#pragma unroll
            for (int kb = 0; kb < 2; kb++) {
                uint64_t dP = mk_desc(sb + SM_P + kb * 16384);
                uint64_t dV = mk_desc(sb + SM_VT + kb * 8192);
#pragma unroll
                for (int ks = 0; ks < 4; ks++) {
                    uint32_t en0 = (kt == 0 && kb == 0 && ks == 0) ? 0u : 1u;
                    mma_f16_ss(tmem + 128, dP + 2 * ks, dV + 2 * ks, IDESC_O, en0);
                }
            }
            tc_commit(sb + 16);
        }
    }
    mbar_wait(sb + 16, (uint32_t)(oph & 1)); oph++;
    TC_FENCE_AFTER();

    float* lred = (float*)(sm + SM_P);
    lred[tid] = lpart;
    __syncthreads();
    if (wid < 4) {
        uint32_t o0[32], o1[32];
        TC_LD_X32(o0, tmem + 128);
        TC_LD_X32(o1, tmem + 160);
        TC_WAIT_LD();
        TC_FENCE_BEFORE();
        int r = wid * 32 + lane;
        float inv = 1.f / (lred[r] + lred[r + 128]);
        int b = bh >> 4, h = bh & 15;
        int s = qt * 128 + r;
        uint32_t* ph = (uint32_t*)(outh + ((size_t)(b * SS + s)) * DD + h * 64);
#pragma unroll
        for (int m = 0; m < 32; m++) {
            int c0 = 2 * m, c1 = 2 * m + 1;
            float v0 = __uint_as_float(c0 < 32 ? o0[c0] : o1[c0 - 32]) * inv;
            float v1 = __uint_as_float(c1 < 32 ? o0[c1] : o1[c1 - 32]) * inv;
            ph[m] = pack_h2(v0, v1);
        }
    }
    __syncthreads();
    if (wid == 0) { TC_DEALLOC(tmem, 256); }

#else
    // compact fallback: one row per thread (never runs with sm_103a SASS)
    if (tid < 128) {
        int r = qt * 128 + tid;
        const fp16* Q = g_qkv[0] + ((size_t)bh * SS + r) * DH;
        float acc[DH];
        for (int d = 0; d < DH; d++) acc[d] = 0.f;
        float l = 0.f;
        for (int s = 0; s < SS; s++) {
            const fp16* Kp = g_qkv[1] + ((size_t)bh * SS + s) * DH;
            const fp16* Vp = g_qkv[2] + ((size_t)bh * SS + s) * DH;
            float sc = 0.f;
            for (int d = 0; d < DH; d++) sc += __half2float(Q[d]) * __half2float(Kp[d]);
            float p = expf(sc * 0.125f);
            l += p;
            for (int d = 0; d < DH; d++) acc[d] += p * __half2float(Vp[d]);
        }
        int b = bh >> 4, h = bh & 15;
        fp16* o = outh + ((size_t)(b * SS + r)) * DD + h * 64;
        for (int d = 0; d < DH; d++) o[d] = __float2half_rn(acc[d] / l);
    }
#endif
#endif
}

// ---------------- router ----------------
__global__ void zero_cnt_kernel() { if (threadIdx.x < NE) g_cnt[threadIdx.x] = 0; }

__global__ void router_kernel(const float* __restrict__ xn2, const float* __restrict__ wr)
{
    int t = blockIdx.x, lane = threadIdx.x;
    float p[NE];
#pragma unroll
    for (int e = 0; e < NE; e++) p[e] = 0.f;
    const float* xr = xn2 + (size_t)t * DD;
    for (int d = lane; d < DD; d += 32) {
        float xv = xr[d];
        const float* wrow = wr + (size_t)d * NE;
#pragma unroll
        for (int e = 0; e < NE; e++) p[e] = fmaf(xv, wrow[e], p[e]);
    }
#pragma unroll
    for (int e = 0; e < NE; e++)
        for (int o = 16; o > 0; o >>= 1) p[e] += __shfl_xor_sync(0xffffffffu, p[e], o);
    if (lane == 0) {
        float m = p[0];
#pragma unroll
        for (int e = 1; e < NE; e++) m = fmaxf(m, p[e]);
        float pr[NE], sum = 0.f;
#pragma unroll
        for (int e = 0; e < NE; e++) { pr[e] = expf(p[e] - m); sum += pr[e]; }
        float inv = 1.f / sum;
#pragma unroll
        for (int e = 0; e < NE; e++) pr[e] *= inv;
        g_zz[t] = m + logf(sum);
#pragma unroll
        for (int e = 0; e < NE; e++) g_probs[t * NE + e] = pr[e];
        int i0 = 0; float v0 = pr[0];
#pragma unroll
        for (int e = 1; e < NE; e++) if (pr[e] > v0) { v0 = pr[e]; i0 = e; }
        int i1 = -1; float v1 = -1.f;
#pragma unroll
        for (int e = 0; e < NE; e++) { if (e == i0) continue; if (pr[e] > v1) { v1 = pr[e]; i1 = e; } }
        float w0 = v0 / (v0 + v1), w1 = v1 / (v0 + v1);
        int r0 = atomicAdd(&g_cnt[i0], 1); g_rowlist[i0 * TT + r0] = t;
        int r1 = atomicAdd(&g_cnt[i1], 1); g_rowlist[i1 * TT + r1] = t;
        g_slot_e[2 * t]     = i0; g_slot_r[2 * t]     = r0; g_slot_w[2 * t]     = w0;
        g_slot_e[2 * t + 1] = i1; g_slot_r[2 * t + 1] = r1; g_slot_w[2 * t + 1] = w1;
    }
}

// ---------------- loss ----------------
__global__ void loss_kernel(float* __restrict__ out, int out_size)
{
    int tid = threadIdx.x;
    __shared__ float red[256];
    __shared__ float sumsp[NE];
    __shared__ float sumz;
    float accp[NE];
#pragma unroll
    for (int e = 0; e < NE; e++) accp[e] = 0.f;
    float accz = 0.f;
    for (int t = tid; t < TT; t += 256) {
        float z = g_zz[t];
        accz += z * z;
#pragma unroll
        for (int e = 0; e < NE; e++) accp[e] += g_probs[t * NE + e];
    }
    red[tid] = accz; __syncthreads();
    for (int o = 128; o > 0; o >>= 1) { if (tid < o) red[tid] += red[tid + o]; __syncthreads(); }
    if (tid == 0) sumz = red[0];
    __syncthreads();
    for (int e = 0; e < NE; e++) {
        red[tid] = accp[e]; __syncthreads();
        for (int o = 128; o > 0; o >>= 1) { if (tid < o) red[tid] += red[tid + o]; __syncthreads(); }
        if (tid == 0) sumsp[e] = red[0];
        __syncthreads();
    }
    if (tid == 0) {
        float aux = 0.f;
        for (int e = 0; e < NE; e++)
            aux += ((float)g_cnt[e] / (float)TT) * (sumsp[e] / (float)TT);
        aux *= (float)NE / 2.f;
        float loss = aux + 0.001f * (sumz / (float)TT);
        for (int i = NMAIN; i < out_size; i++) out[i] = loss;
    }
}

// ---------------- combine ----------------
__global__ void combine_kernel(float* __restrict__ out)
{
    int idx = blockIdx.x * 256 + threadIdx.x;
    if (idx >= NMAIN) return;
    int t = idx >> 10, d = idx & 1023;
    int e0 = g_slot_e[2 * t], r0 = g_slot_r[2 * t];
    int e1 = g_slot_e[2 * t + 1], r1 = g_slot_r[2 * t + 1];
    out[idx] = g_x2[idx]
             + g_slot_w[2 * t]     * g_Y[((size_t)e0 * TT + r0) * DD + d]
             + g_slot_w[2 * t + 1] * g_Y[((size_t)e1 * TT + r1) * DD + d];
}

// ---------------- launch ----------------
extern "C" void kernel_launch(void* const* d_in, const int* in_sizes, int n_in,
                              void* d_out, int out_size)
{
    const float* x   = (const float*)d_in[0];
    const float* ln1 = (const float*)d_in[1];
    const float* ln2 = (const float*)d_in[2];
    const float* wq  = (const float*)d_in[3];
    const float* wk  = (const float*)d_in[4];
    const float* wv  = (const float*)d_in[5];
    const float* wo  = (const float*)d_in[6];
    const float* wr  = (const float*)d_in[7];
    const float* w1  = (const float*)d_in[8];
    const float* w2  = (const float*)d_in[9];
    float* out = (float*)d_out;

    cudaFuncSetAttribute(tc_attn, cudaFuncAttributeMaxDynamicSharedMemorySize, ATT_SMEM);
    cudaFuncSetAttribute(tc_gemm<GM_QKV>,  cudaFuncAttributeMaxDynamicSharedMemorySize, G_SMEM);
    cudaFuncSetAttribute(tc_gemm<GM_RES>,  cudaFuncAttributeMaxDynamicSharedMemorySize, G_SMEM);
    cudaFuncSetAttribute(tc_gemm<GM_MOE1>, cudaFuncAttributeMaxDynamicSharedMemorySize, G_SMEM);
    cudaFuncSetAttribute(tc_gemm<GM_MOE2>, cudaFuncAttributeMaxDynamicSharedMemorySize, G_SMEM);

    fp16 *p_xn, *p_xn2, *p_ctx, *p_wpth, *p_wptl, *p_w1th, *p_w1tl, *p_w2th, *p_w2tl, *p_H;
    float *p_xn2f, *p_x2, *p_Y;
    cudaGetSymbolAddress((void**)&p_xn,   g_xn);
    cudaGetSymbolAddress((void**)&p_xn2,  g_xn2);
    cudaGetSymbolAddress((void**)&p_xn2f, g_xn2f);
    cudaGetSymbolAddress((void**)&p_ctx,  g_ctx);
    cudaGetSymbolAddress((void**)&p_x2,   g_x2);
    cudaGetSymbolAddress((void**)&p_wpth, g_wpth);
    cudaGetSymbolAddress((void**)&p_wptl, g_wptl);
    cudaGetSymbolAddress((void**)&p_w1th, g_w1th);
    cudaGetSymbolAddress((void**)&p_w1tl, g_w1tl);
    cudaGetSymbolAddress((void**)&p_w2th, g_w2th);
    cudaGetSymbolAddress((void**)&p_w2tl, g_w2tl);
    cudaGetSymbolAddress((void**)&p_H,    g_H);
    cudaGetSymbolAddress((void**)&p_Y,    g_Y);

    dim3 bt(256);
    wt_convert_kernel<<<dim3(DD/64, DD/64, 1), bt>>>(wq, p_wpth,           p_wptl,           DD, DD);
    wt_convert_kernel<<<dim3(DD/64, DD/64, 1), bt>>>(wk, p_wpth + DD*DD,   p_wptl + DD*DD,   DD, DD);
    wt_convert_kernel<<<dim3(DD/64, DD/64, 1), bt>>>(wv, p_wpth + 2*DD*DD, p_wptl + 2*DD*DD, DD, DD);
    wt_convert_kernel<<<dim3(DD/64, DD/64, 1), bt>>>(wo, p_wpth + 3*DD*DD, p_wptl + 3*DD*DD, DD, DD);

    rmsnorm_kernel<<<TT, 256>>>(x, ln1, nullptr, p_xn);

    // launch 5 (ncu -s 5): QKV projections
    tc_gemm<GM_QKV><<<dim3(DD/256, TT/128, 3), 256, G_SMEM>>>(
        p_xn, p_wpth, p_wptl, nullptr, nullptr, nullptr, TT, DD, DD);

    wt_convert_kernel<<<dim3(FF/64, DD/64, NE), bt>>>(w1, p_w1th, p_w1tl, DD, FF);
    wt_convert_kernel<<<dim3(DD/64, FF/64, NE), bt>>>(w2, p_w2th, p_w2tl, FF, DD);

    tc_attn<<<dim3(BB * NH, SS / 128), 256, ATT_SMEM>>>(p_ctx);

    tc_gemm<GM_RES><<<dim3(DD/256, TT/128, 1), 256, G_SMEM>>>(
        p_ctx, p_wpth + 3*DD*DD, p_wptl + 3*DD*DD, p_x2, x, nullptr, TT, DD, DD);

    rmsnorm_kernel<<<TT, 256>>>(p_x2, ln2, p_xn2f, p_xn2);

    zero_cnt_kernel<<<1, 32>>>();
    router_kernel<<<TT, 32>>>(p_xn2f, wr);
    loss_kernel<<<1, 256>>>(out, out_size);

    tc_gemm<GM_MOE1><<<dim3(FF/256, TT/128, NE), 256, G_SMEM>>>(
        p_xn2, p_w1th, p_w1tl, nullptr, nullptr, p_H, TT, FF, DD);
    tc_gemm<GM_MOE2><<<dim3(DD/256, TT/128, NE), 256, G_SMEM>>>(
        p_H, p_w2th, p_w2tl, p_Y, nullptr, nullptr, TT, DD, FF);

    combine_kernel<<<(NMAIN + 255) / 256, 256>>>(out);
}

// round 10
// speedup vs baseline: 3.2380x; 1.5386x over previous
#include <cuda_runtime.h>
#include <cuda_fp16.h>
#include <math.h>
#include <stdint.h>

#define BB 2
#define SS 2048
#define DD 1024
#define NH 16
#define DH 64
#define NE 8
#define FF 4096
#define TT (BB*SS)
#define NMAIN (TT*DD)

typedef __half fp16;

__device__ fp16  g_xn[TT*DD];
__device__ float g_xn2f[TT*DD];
__device__ fp16  g_xn2[TT*DD];
__device__ fp16  g_qkv[3][(size_t)TT*DD];
__device__ fp16  g_ctx[TT*DD];
__device__ float g_x2[TT*DD];
__device__ fp16  g_wpt[4*DD*DD];
__device__ fp16  g_w1t[(size_t)NE*DD*FF];
__device__ fp16  g_w2t[(size_t)NE*DD*FF];
__device__ fp16  g_H[(size_t)NE*TT*FF];
__device__ float g_Y[(size_t)NE*TT*DD];
__device__ float g_probs[TT*NE];
__device__ float g_zz[TT];
__device__ int   g_cnt[NE];
__device__ int   g_rowlist[NE*TT];
__device__ int   g_slot_e[2*TT];
__device__ int   g_slot_r[2*TT];
__device__ float g_slot_w[2*TT];

__device__ __forceinline__ uint32_t smem_u32(const void* p) {
    uint32_t a;
    asm("{ .reg .u64 t; cvta.to.shared.u64 t, %1; cvt.u32.u64 %0, t; }" : "=r"(a) : "l"(p));
    return a;
}
__device__ __forceinline__ uint32_t elect1() {
    uint32_t p;
    asm volatile("{\n.reg .pred p;\nelect.sync _|p, 0xFFFFFFFF;\nselp.b32 %0, 1, 0, p;\n}" : "=r"(p));
    return p;
}
__device__ __forceinline__ void mbar_init(uint32_t a, uint32_t n) {
    asm volatile("mbarrier.init.shared.b64 [%0], %1;" :: "r"(a), "r"(n) : "memory");
}
__device__ __forceinline__ void mbar_wait(uint32_t a, uint32_t par) {
    asm volatile(
        "{\n.reg .pred P;\nLW%=:\n"
        "mbarrier.try_wait.parity.acquire.cta.shared::cta.b64 P, [%0], %1, 0x989680;\n"
        "@P bra LD%=;\nbra LW%=;\nLD%=:\n}" :: "r"(a), "r"(par) : "memory");
}
__device__ __forceinline__ uint64_t mk_desc(uint32_t addr) {
    return ((uint64_t)2 << 61) | ((uint64_t)1 << 46) | ((uint64_t)64 << 32)
         | ((uint64_t)1 << 16) | ((addr >> 4) & 0x3FFF);
}
__device__ __forceinline__ void tc_commit(uint32_t mbar) {
#if defined(__CUDA_ARCH_FEAT_SM103_ALL)
    asm volatile("tcgen05.commit.cta_group::1.mbarrier::arrive::one.shared::cluster.b64 [%0];"
                 :: "r"(mbar) : "memory");
#endif
}
__device__ __forceinline__ void mma_f16_ss(uint32_t d, uint64_t ad, uint64_t bd,
                                           uint32_t idesc, uint32_t en) {
#if defined(__CUDA_ARCH_FEAT_SM103_ALL)
    asm volatile(
        "{\n.reg .pred p;\nsetp.ne.u32 p, %4, 0;\n"
        "tcgen05.mma.cta_group::1.kind::f16 [%0], %1, %2, %3, {%5, %5, %5, %5}, p;\n}"
        :: "r"(d), "l"(ad), "l"(bd), "r"(idesc), "r"(en), "r"(0u) : "memory");
#endif
}

#if defined(__CUDA_ARCH_FEAT_SM103_ALL)
#define TC_ALLOC(sbaddr, n) \
    asm volatile("tcgen05.alloc.cta_group::1.sync.aligned.shared::cta.b32 [%0], %1;" \
                 :: "r"(sbaddr), "r"((uint32_t)(n)) : "memory")
#define TC_RELINQ() asm volatile("tcgen05.relinquish_alloc_permit.cta_group::1.sync.aligned;")
#define TC_DEALLOC(t, n) \
    asm volatile("tcgen05.dealloc.cta_group::1.sync.aligned.b32 %0, %1;" :: "r"(t), "r"((uint32_t)(n)))
#define TC_FENCE_AFTER()  asm volatile("tcgen05.fence::after_thread_sync;" ::: "memory")
#define TC_FENCE_BEFORE() asm volatile("tcgen05.fence::before_thread_sync;" ::: "memory")
#define TC_WAIT_LD()      asm volatile("tcgen05.wait::ld.sync.aligned;" ::: "memory")
#define TC_LD_X32(r, ta) \
    asm volatile( \
        "tcgen05.ld.sync.aligned.32x32b.x32.b32 " \
        "{%0, %1, %2, %3, %4, %5, %6, %7, %8, %9, %10, %11, %12, %13, %14, %15, " \
        " %16, %17, %18, %19, %20, %21, %22, %23, %24, %25, %26, %27, %28, %29, %30, %31}, [%32];" \
        : "=r"((r)[0]),  "=r"((r)[1]),  "=r"((r)[2]),  "=r"((r)[3]), \
          "=r"((r)[4]),  "=r"((r)[5]),  "=r"((r)[6]),  "=r"((r)[7]), \
          "=r"((r)[8]),  "=r"((r)[9]),  "=r"((r)[10]), "=r"((r)[11]), \
          "=r"((r)[12]), "=r"((r)[13]), "=r"((r)[14]), "=r"((r)[15]), \
          "=r"((r)[16]), "=r"((r)[17]), "=r"((r)[18]), "=r"((r)[19]), \
          "=r"((r)[20]), "=r"((r)[21]), "=r"((r)[22]), "=r"((r)[23]), \
          "=r"((r)[24]), "=r"((r)[25]), "=r"((r)[26]), "=r"((r)[27]), \
          "=r"((r)[28]), "=r"((r)[29]), "=r"((r)[30]), "=r"((r)[31]) \
        : "r"(ta))
#endif

__device__ __forceinline__ float gelu_tanh(float x) {
    float x3 = x * x * x;
    return 0.5f * x * (1.f + tanhf(0.7978845608028654f * (x + 0.044715f * x3)));
}
__device__ __forceinline__ uint32_t pack_h2(float a, float b) {
    __half2 h = __floats2half2_rn(a, b);
    return *(uint32_t*)&h;
}

// ---------------- rmsnorm (vectorized; optional fp32 out + fp16 out) --------
__global__ void rmsnorm_kernel(const float* __restrict__ x, const float* __restrict__ w,
                               float* __restrict__ yf, fp16* __restrict__ yh)
{
    int row = blockIdx.x, tid = threadIdx.x;
    const float* xr = x + (size_t)row * DD;
    int d4 = tid * 4;
    float4 xv = *(const float4*)(xr + d4);
    float s = xv.x * xv.x + xv.y * xv.y + xv.z * xv.z + xv.w * xv.w;
    __shared__ float red[8];
    for (int o = 16; o > 0; o >>= 1) s += __shfl_xor_sync(0xffffffffu, s, o);
    if ((tid & 31) == 0) red[tid >> 5] = s;
    __syncthreads();
    float tot = 0.f;
#pragma unroll
    for (int i = 0; i < 8; i++) tot += red[i];
    float inv = rsqrtf(tot / (float)DD + 1e-6f);
    float4 wv = *(const float4*)(w + d4);
    float v0 = xv.x * inv * wv.x, v1 = xv.y * inv * wv.y;
    float v2 = xv.z * inv * wv.z, v3 = xv.w * inv * wv.w;
    if (yf) *(float4*)(yf + (size_t)row * DD + d4) = make_float4(v0, v1, v2, v3);
    uint2 p; p.x = pack_h2(v0, v1); p.y = pack_h2(v2, v3);
    *(uint2*)(yh + (size_t)row * DD + d4) = p;
}

// ---------------- weight transpose -> fp16 (hi only) -----------------------
__global__ void wt_convert_kernel(const float* __restrict__ W,
                                  fp16* __restrict__ Th, int K, int N)
{
    __shared__ float tile[64][68];
    size_t zoff = (size_t)blockIdx.z * K * N;
    int n0 = blockIdx.x * 64, k0 = blockIdx.y * 64;
    int tx = threadIdx.x & 15, ty = threadIdx.x >> 4;
#pragma unroll
    for (int i = 0; i < 4; i++) {
        int r = ty + 16 * i;
        *(float4*)&tile[r][tx * 4] = *(const float4*)(W + zoff + (size_t)(k0 + r) * N + n0 + tx * 4);
    }
    __syncthreads();
#pragma unroll
    for (int i = 0; i < 4; i++) {
        int n = ty + 16 * i, kk = tx * 4;
        size_t idx = zoff + (size_t)(n0 + n) * K + k0 + kk;
        *(uint2*)(Th + idx) = make_uint2(pack_h2(tile[kk][n], tile[kk + 1][n]),
                                         pack_h2(tile[kk + 2][n], tile[kk + 3][n]));
    }
}

#define GM_QKV  1
#define GM_RES  2
#define GM_MOE1 3
#define GM_MOE2 4
#define BUF_BYTES 49152
#define G_SMEM  (1024 + 2 * BUF_BYTES)   // 99328 -> 2 CTAs/SM

// ---------------- tcgen05 GEMM: C[128x256], fp16 single-term, 2 CTA/SM -----
template<int MODE>
__global__ void __launch_bounds__(256, 2)
tc_gemm(const fp16* __restrict__ A, const fp16* __restrict__ B0,
        float* __restrict__ Cf, const float* __restrict__ Res,
        fp16* __restrict__ Ch, int M, int N, int K)
{
#if defined(__CUDA_ARCH__)
    extern __shared__ char sm[];
    int tid = threadIdx.x;
    int e  = blockIdx.z;
    int m0 = blockIdx.y * 128, n0 = blockIdx.x * 256;
    int Me = M;
    const fp16* B = B0;
    if (MODE == GM_MOE1 || MODE == GM_MOE2) {
        Me = g_cnt[e];
        if (m0 >= Me) return;
        B += (size_t)e * (size_t)K * N;
    } else if (MODE == GM_QKV) {
        B += (size_t)e * (size_t)K * N;
    }

#if defined(__CUDA_ARCH_FEAT_SM103_ALL)
    uint32_t sb = smem_u32(sm);
    int wid = tid >> 5, lid = tid & 31;
    int nk = K / 64;

    auto issue_fill = [&](int kc, int bufi) {
        uint32_t tb = sb + 1024 + (uint32_t)bufi * BUF_BYTES;
        for (int task = tid; task < 384; task += 256) {
            if (task < 128) {
                int gr = m0 + task;
                bool val = gr < Me;
                size_t ri = 0;
                if (val) {
                    if (MODE == GM_MOE1)      ri = (size_t)g_rowlist[e * TT + gr];
                    else if (MODE == GM_MOE2) ri = (size_t)e * TT + gr;
                    else                      ri = (size_t)gr;
                }
                const char* src = (const char*)(A + ri * (size_t)K + kc * 64);
                uint32_t sz = val ? 16u : 0u;
#pragma unroll
                for (int j = 0; j < 8; j++) {
                    uint32_t off = (uint32_t)task * 128u + j * 16u;
                    uint32_t swz = off ^ ((off >> 3) & 0x70);
                    asm volatile("cp.async.cg.shared.global [%0], [%1], 16, %2;"
                                 :: "r"(tb + swz), "l"(src + j * 16), "r"(sz) : "memory");
                }
            } else {
                int row = task - 128;
                const char* src = (const char*)(B + (size_t)(n0 + row) * K + kc * 64);
#pragma unroll
                for (int j = 0; j < 8; j++) {
                    uint32_t off = (uint32_t)row * 128u + j * 16u;
                    uint32_t swz = off ^ ((off >> 3) & 0x70);
                    asm volatile("cp.async.cg.shared.global [%0], [%1], 16;"
                                 :: "r"(tb + 16384 + swz), "l"(src + j * 16) : "memory");
                }
            }
        }
        asm volatile("cp.async.commit_group;" ::: "memory");
    };

    issue_fill(0, 0);
    if (nk > 1) issue_fill(1, 1);

    if (wid == 0) { TC_ALLOC(sb, 256); TC_RELINQ(); }
    if (tid == 0) { mbar_init(sb + 8, 1); mbar_init(sb + 16, 1); }
    __syncthreads();
    uint32_t tmem;
    asm volatile("ld.shared.b32 %0, [%1];" : "=r"(tmem) : "r"(sb));

    const uint32_t IDESC = (1u << 4) | (32u << 17) | (8u << 24);   // f16 in, f32 acc, N=256, M=128
    int ph0 = 0, ph1 = 0;
    for (int kc = 0; kc < nk; kc++) {
        int b = kc & 1;
        if (kc >= 1 && kc + 1 < nk) {
            int nb = 1 - b;
            if (nb == 0) { mbar_wait(sb + 8,  (uint32_t)(ph0 & 1)); ph0++; }
            else         { mbar_wait(sb + 16, (uint32_t)(ph1 & 1)); ph1++; }
            issue_fill(kc + 1, nb);
        }
        if (kc + 1 < nk) asm volatile("cp.async.wait_group 1;" ::: "memory");
        else             asm volatile("cp.async.wait_group 0;" ::: "memory");
        asm volatile("fence.proxy.async.shared::cta;" ::: "memory");
        __syncthreads();
        if (wid == 0 && elect1()) {
            uint32_t tb = sb + 1024 + (uint32_t)b * BUF_BYTES;
            uint64_t dA = mk_desc(tb);
            uint64_t dB = mk_desc(tb + 16384);
#pragma unroll
            for (int s = 0; s < 4; s++)
                mma_f16_ss(tmem, dA + 2 * s, dB + 2 * s, IDESC, (kc == 0 && s == 0) ? 0u : 1u);
            tc_commit(sb + 8 + b * 8);
        }
    }
    {
        int lb = (nk - 1) & 1;
        if (lb == 0) mbar_wait(sb + 8,  (uint32_t)(ph0 & 1));
        else         mbar_wait(sb + 16, (uint32_t)(ph1 & 1));
    }
    TC_FENCE_AFTER();

    int rw = wid & 3, cw = wid >> 2;
    int rows_here = Me - m0; if (rows_here > 128) rows_here = 128;
    float* Cs = (float*)(sm + 1024);
#pragma unroll 1
    for (int p = 0; p < 2; p++) {
        uint32_t d0[32], d1[32];
        TC_LD_X32(d0, tmem + p * 128 + cw * 64);
        TC_LD_X32(d1, tmem + p * 128 + cw * 64 + 32);
        TC_WAIT_LD();
        TC_FENCE_BEFORE();
        __syncthreads();
        {
            int rr = rw * 32 + lid, cb = cw * 64;
#pragma unroll
            for (int j = 0; j < 32; j++) {
                Cs[rr * 129 + cb + j]      = __uint_as_float(d0[j]);
                Cs[rr * 129 + cb + 32 + j] = __uint_as_float(d1[j]);
            }
        }
        __syncthreads();
#pragma unroll 4
        for (int it = 0; it < 16; it++) {
            int idx4 = (it * 256 + tid) * 4;
            int rr = idx4 >> 7, cc = idx4 & 127;
            if (rr >= rows_here) continue;
            float v0 = Cs[rr * 129 + cc + 0], v1 = Cs[rr * 129 + cc + 1];
            float v2 = Cs[rr * 129 + cc + 2], v3 = Cs[rr * 129 + cc + 3];
            int colb = n0 + p * 128 + cc;
            if (MODE == GM_RES) {
                size_t o = (size_t)(m0 + rr) * N + colb;
                float4 rs = *(const float4*)(Res + o);
                *(float4*)(Cf + o) = make_float4(v0 + rs.x, v1 + rs.y, v2 + rs.z, v3 + rs.w);
            } else if (MODE == GM_MOE2) {
                size_t o = ((size_t)e * TT + m0 + rr) * N + colb;
                *(float4*)(Cf + o) = make_float4(v0, v1, v2, v3);
            } else if (MODE == GM_MOE1) {
                size_t o = ((size_t)e * TT + m0 + rr) * N + colb;
                uint2 ph;
                ph.x = pack_h2(gelu_tanh(v0), gelu_tanh(v1));
                ph.y = pack_h2(gelu_tanh(v2), gelu_tanh(v3));
                *(uint2*)(Ch + o) = ph;
            } else {
                int row = m0 + rr;
                int b2 = row >> 11, s5 = row & (SS - 1);
                int h = colb >> 6, dh = colb & 63;
                size_t o = (((size_t)(b2 * NH + h)) * SS + s5) * DH + dh;
                uint2 ph; ph.x = pack_h2(v0, v1); ph.y = pack_h2(v2, v3);
                *(uint2*)(g_qkv[e] + o) = ph;
            }
        }
        __syncthreads();
    }
    if (wid == 0) { TC_DEALLOC(tmem, 256); }

#else
    // compact SIMT fallback (never runs when sm_103a SASS is loaded)
    for (int i = tid; i < 128 * 256; i += 256) {
        int rr = i >> 8, cc = i & 255;
        int row = m0 + rr;
        if (row >= Me) continue;
        size_t ri;
        if (MODE == GM_MOE1)      ri = (size_t)g_rowlist[e * TT + row];
        else if (MODE == GM_MOE2) ri = (size_t)e * TT + row;
        else                      ri = (size_t)row;
        float acc = 0.f;
        const fp16* ar = A + ri * (size_t)K;
        const fp16* br = B + (size_t)(n0 + cc) * K;
        for (int k = 0; k < K; k++)
            acc += __half2float(ar[k]) * __half2float(br[k]);
        if (MODE == GM_RES) { size_t o = (size_t)row * N + n0 + cc; Cf[o] = acc + Res[o]; }
        else if (MODE == GM_MOE2) Cf[((size_t)e * TT + row) * N + n0 + cc] = acc;
        else if (MODE == GM_MOE1) Ch[((size_t)e * TT + row) * N + n0 + cc] = __float2half_rn(gelu_tanh(acc));
        else {
            int col = n0 + cc, b2 = row >> 11, s5 = row & (SS - 1);
            g_qkv[e][(((size_t)(b2 * NH + (col >> 6))) * SS + s5) * DH + (col & 63)] = __float2half_rn(acc);
        }
    }
#endif
#endif
}

// ---------------- tcgen05 flash attention, fp16 single-term, 2 CTA/SM ------
#define SM_Q   1024
#define SM_K   17408
#define SM_VST 33792
#define SM_VT  50176
#define SM_P   66560
#define ATT_SMEM 100352

__global__ void __launch_bounds__(256, 2)
tc_attn(fp16* __restrict__ outh)
{
#if defined(__CUDA_ARCH__)
    extern __shared__ char sm[];
    int tid = threadIdx.x;
    int bh = blockIdx.x;
    int qt = blockIdx.y;

#if defined(__CUDA_ARCH_FEAT_SM103_ALL)
    uint32_t sb = smem_u32(sm);
    int wid = tid >> 5, lane = tid & 31;

    auto fill_kv = [&](int kt) {
        int arr = tid >> 7, r = tid & 127;
        const fp16* src = (arr == 0 ? g_qkv[1] : g_qkv[2]);
        uint32_t dstb = (arr == 0 ? sb + SM_K : sb + SM_VST);
        const char* s4 = (const char*)(src + ((size_t)bh * SS + kt * 128 + r) * DH);
        if (arr == 0) {
#pragma unroll
            for (int j = 0; j < 8; j++) {
                uint32_t off = (uint32_t)r * 128u + j * 16u;
                uint32_t swz = off ^ ((off >> 3) & 0x70);
                asm volatile("cp.async.cg.shared.global [%0], [%1], 16;"
                             :: "r"(dstb + swz), "l"(s4 + j * 16) : "memory");
            }
        } else {
#pragma unroll
            for (int j = 0; j < 8; j++)
                asm volatile("cp.async.cg.shared.global [%0], [%1], 16;"
                             :: "r"(dstb + (uint32_t)r * 128u + j * 16u), "l"(s4 + j * 16) : "memory");
        }
        asm volatile("cp.async.commit_group;" ::: "memory");
    };

    fill_kv(0);

    if (wid == 0) { TC_ALLOC(sb, 256); TC_RELINQ(); }
    if (tid == 0) { mbar_init(sb + 8, 1); mbar_init(sb + 16, 1); }
    __syncthreads();
    uint32_t tmem;
    asm volatile("ld.shared.b32 %0, [%1];" : "=r"(tmem) : "r"(sb));

    {
        int r = tid & 127, j0 = (tid >> 7) * 4;
        const uint4* s4 = (const uint4*)(g_qkv[0] + ((size_t)bh * SS + qt * 128 + r) * DH);
#pragma unroll
        for (int j = 0; j < 4; j++) {
            uint32_t off = (uint32_t)r * 128u + (j0 + j) * 16u;
            uint32_t swz = off ^ ((off >> 3) & 0x70);
            *(uint4*)(sm + SM_Q + swz) = s4[j0 + j];
        }
    }

    const uint32_t IDESC_S = (1u << 4) | (16u << 17) | (8u << 24);
    const uint32_t IDESC_O = (1u << 4) | (8u << 17)  | (8u << 24);
    int sph = 0, oph = 0;
    float lpart = 0.f;
    const int NKT = SS / 128;

    for (int kt = 0; kt < NKT; kt++) {
        if (kt > 0) { mbar_wait(sb + 16, (uint32_t)(oph & 1)); oph++; }
        asm volatile("cp.async.wait_group 0;" ::: "memory");
        asm volatile("fence.proxy.async.shared::cta;" ::: "memory");
        __syncthreads();

        if (wid == 0 && elect1()) {
            uint64_t dQ = mk_desc(sb + SM_Q);
            uint64_t dK = mk_desc(sb + SM_K);
#pragma unroll
            for (int ks = 0; ks < 4; ks++)
                mma_f16_ss(tmem, dQ + 2 * ks, dK + 2 * ks, IDESC_S, ks == 0 ? 0u : 1u);
            tc_commit(sb + 8);
        }

        {
            int d = tid & 63, shb = (tid >> 6) & 1, mh = tid >> 7;
            const unsigned short* vs = (const unsigned short*)(sm + SM_VST);
            char* vt = sm + SM_VT + shb * 8192;
#pragma unroll
            for (int i = 0; i < 16; i++) {
                int m = mh * 16 + i;
                int s0 = shb * 64 + 2 * m;
                uint32_t u = (uint32_t)vs[s0 * 64 + d] | ((uint32_t)vs[(s0 + 1) * 64 + d] << 16);
                uint32_t off = (uint32_t)d * 128u + m * 4u;
                uint32_t swz = off ^ ((off >> 3) & 0x70);
                *(uint32_t*)(vt + swz) = u;
            }
        }
        asm volatile("fence.proxy.async.shared::cta;" ::: "memory");
        __syncthreads();

        mbar_wait(sb + 8, (uint32_t)(sph & 1)); sph++;
        TC_FENCE_AFTER();

        if (kt + 1 < NKT) fill_kv(kt + 1);

        {
            int rw = wid & 3, cw = wid >> 2;
            uint32_t s0[32], s1[32];
            TC_LD_X32(s0, tmem + cw * 64);
            TC_LD_X32(s1, tmem + cw * 64 + 32);
            TC_WAIT_LD();
            TC_FENCE_BEFORE();
            int r = rw * 32 + lane;
            char* pb = sm + SM_P + cw * 16384;
#pragma unroll
            for (int m = 0; m < 32; m++) {
                int c0 = 2 * m, c1 = 2 * m + 1;
                float a = __uint_as_float(c0 < 32 ? s0[c0] : s1[c0 - 32]);
                float b = __uint_as_float(c1 < 32 ? s0[c1] : s1[c1 - 32]);
                float pa = __expf(a * 0.125f);
                float pbv = __expf(b * 0.125f);
                lpart += pa + pbv;
                uint32_t off = (uint32_t)r * 128u + m * 4u;
                uint32_t swz = off ^ ((off >> 3) & 0x70);
                *(uint32_t*)(pb + swz) = pack_h2(pa, pbv);
            }
        }
        asm volatile("fence.proxy.async.shared::cta;" ::: "memory");
        __syncthreads();

        if (wid == 0 && elect1()) {
#pragma unroll
            for (int kb = 0; kb < 2; kb++) {
                uint64_t dP = mk_desc(sb + SM_P + kb * 16384);
                uint64_t dV = mk_desc(sb + SM_VT + kb * 8192);
#pragma unroll
                for (int ks = 0; ks < 4; ks++) {
                    uint32_t en0 = (kt == 0 && kb == 0 && ks == 0) ? 0u : 1u;
                    mma_f16_ss(tmem + 128, dP + 2 * ks, dV + 2 * ks, IDESC_O, en0);
                }
            }
            tc_commit(sb + 16);
        }
    }
    mbar_wait(sb + 16, (uint32_t)(oph & 1)); oph++;
    TC_FENCE_AFTER();

    float* lred = (float*)(sm + SM_P);
    lred[tid] = lpart;
    __syncthreads();
    if (wid < 4) {
        uint32_t o0[32], o1[32];
        TC_LD_X32(o0, tmem + 128);
        TC_LD_X32(o1, tmem + 160);
        TC_WAIT_LD();
        TC_FENCE_BEFORE();
        int r = wid * 32 + lane;
        float inv = 1.f / (lred[r] + lred[r + 128]);
        int b = bh >> 4, h = bh & 15;
        int s = qt * 128 + r;
        uint32_t* ph = (uint32_t*)(outh + ((size_t)(b * SS + s)) * DD + h * 64);
#pragma unroll
        for (int m = 0; m < 32; m++) {
            int c0 = 2 * m, c1 = 2 * m + 1;
            float v0 = __uint_as_float(c0 < 32 ? o0[c0] : o1[c0 - 32]) * inv;
            float v1 = __uint_as_float(c1 < 32 ? o0[c1] : o1[c1 - 32]) * inv;
            ph[m] = pack_h2(v0, v1);
        }
    }
    __syncthreads();
    if (wid == 0) { TC_DEALLOC(tmem, 256); }

#else
    if (tid < 128) {
        int r = qt * 128 + tid;
        const fp16* Q = g_qkv[0] + ((size_t)bh * SS + r) * DH;
        float acc[DH];
        for (int d = 0; d < DH; d++) acc[d] = 0.f;
        float l = 0.f;
        for (int s = 0; s < SS; s++) {
            const fp16* Kp = g_qkv[1] + ((size_t)bh * SS + s) * DH;
            const fp16* Vp = g_qkv[2] + ((size_t)bh * SS + s) * DH;
            float sc = 0.f;
            for (int d = 0; d < DH; d++) sc += __half2float(Q[d]) * __half2float(Kp[d]);
            float p = expf(sc * 0.125f);
            l += p;
            for (int d = 0; d < DH; d++) acc[d] += p * __half2float(Vp[d]);
        }
        int b = bh >> 4, h = bh & 15;
        fp16* o = outh + ((size_t)(b * SS + r)) * DD + h * 64;
        for (int d = 0; d < DH; d++) o[d] = __float2half_rn(acc[d] / l);
    }
#endif
#endif
}

// ---------------- router ----------------
__global__ void zero_cnt_kernel() { if (threadIdx.x < NE) g_cnt[threadIdx.x] = 0; }

__global__ void router_kernel(const float* __restrict__ xn2, const float* __restrict__ wr)
{
    int t = blockIdx.x, lane = threadIdx.x;
    float p[NE];
#pragma unroll
    for (int e = 0; e < NE; e++) p[e] = 0.f;
    const float* xr = xn2 + (size_t)t * DD;
    for (int d = lane; d < DD; d += 32) {
        float xv = xr[d];
        const float* wrow = wr + (size_t)d * NE;
#pragma unroll
        for (int e = 0; e < NE; e++) p[e] = fmaf(xv, wrow[e], p[e]);
    }
#pragma unroll
    for (int e = 0; e < NE; e++)
        for (int o = 16; o > 0; o >>= 1) p[e] += __shfl_xor_sync(0xffffffffu, p[e], o);
    if (lane == 0) {
        float m = p[0];
#pragma unroll
        for (int e = 1; e < NE; e++) m = fmaxf(m, p[e]);
        float pr[NE], sum = 0.f;
#pragma unroll
        for (int e = 0; e < NE; e++) { pr[e] = expf(p[e] - m); sum += pr[e]; }
        float inv = 1.f / sum;
#pragma unroll
        for (int e = 0; e < NE; e++) pr[e] *= inv;
        g_zz[t] = m + logf(sum);
#pragma unroll
        for (int e = 0; e < NE; e++) g_probs[t * NE + e] = pr[e];
        int i0 = 0; float v0 = pr[0];
#pragma unroll
        for (int e = 1; e < NE; e++) if (pr[e] > v0) { v0 = pr[e]; i0 = e; }
        int i1 = -1; float v1 = -1.f;
#pragma unroll
        for (int e = 0; e < NE; e++) { if (e == i0) continue; if (pr[e] > v1) { v1 = pr[e]; i1 = e; } }
        float w0 = v0 / (v0 + v1), w1 = v1 / (v0 + v1);
        int r0 = atomicAdd(&g_cnt[i0], 1); g_rowlist[i0 * TT + r0] = t;
        int r1 = atomicAdd(&g_cnt[i1], 1); g_rowlist[i1 * TT + r1] = t;
        g_slot_e[2 * t]     = i0; g_slot_r[2 * t]     = r0; g_slot_w[2 * t]     = w0;
        g_slot_e[2 * t + 1] = i1; g_slot_r[2 * t + 1] = r1; g_slot_w[2 * t + 1] = w1;
    }
}

// ---------------- loss ----------------
__global__ void loss_kernel(float* __restrict__ out, int out_size)
{
    int tid = threadIdx.x;
    __shared__ float red[256];
    __shared__ float sumsp[NE];
    __shared__ float sumz;
    float accp[NE];
#pragma unroll
    for (int e = 0; e < NE; e++) accp[e] = 0.f;
    float accz = 0.f;
    for (int t = tid; t < TT; t += 256) {
        float z = g_zz[t];
        accz += z * z;
#pragma unroll
        for (int e = 0; e < NE; e++) accp[e] += g_probs[t * NE + e];
    }
    red[tid] = accz; __syncthreads();
    for (int o = 128; o > 0; o >>= 1) { if (tid < o) red[tid] += red[tid + o]; __syncthreads(); }
    if (tid == 0) sumz = red[0];
    __syncthreads();
    for (int e = 0; e < NE; e++) {
        red[tid] = accp[e]; __syncthreads();
        for (int o = 128; o > 0; o >>= 1) { if (tid < o) red[tid] += red[tid + o]; __syncthreads(); }
        if (tid == 0) sumsp[e] = red[0];
        __syncthreads();
    }
    if (tid == 0) {
        float aux = 0.f;
        for (int e = 0; e < NE; e++)
            aux += ((float)g_cnt[e] / (float)TT) * (sumsp[e] / (float)TT);
        aux *= (float)NE / 2.f;
        float loss = aux + 0.001f * (sumz / (float)TT);
        for (int i = NMAIN; i < out_size; i++) out[i] = loss;
    }
}

// ---------------- combine ----------------
__global__ void combine_kernel(float* __restrict__ out)
{
    int idx = blockIdx.x * 256 + threadIdx.x;
    if (idx >= NMAIN) return;
    int t = idx >> 10, d = idx & 1023;
    int e0 = g_slot_e[2 * t], r0 = g_slot_r[2 * t];
    int e1 = g_slot_e[2 * t + 1], r1 = g_slot_r[2 * t + 1];
    out[idx] = g_x2[idx]
             + g_slot_w[2 * t]     * g_Y[((size_t)e0 * TT + r0) * DD + d]
             + g_slot_w[2 * t + 1] * g_Y[((size_t)e1 * TT + r1) * DD + d];
}

// ---------------- launch ----------------
extern "C" void kernel_launch(void* const* d_in, const int* in_sizes, int n_in,
                              void* d_out, int out_size)
{
    const float* x   = (const float*)d_in[0];
    const float* ln1 = (const float*)d_in[1];
    const float* ln2 = (const float*)d_in[2];
    const float* wq  = (const float*)d_in[3];
    const float* wk  = (const float*)d_in[4];
    const float* wv  = (const float*)d_in[5];
    const float* wo  = (const float*)d_in[6];
    const float* wr  = (const float*)d_in[7];
    const float* w1  = (const float*)d_in[8];
    const float* w2  = (const float*)d_in[9];
    float* out = (float*)d_out;

    cudaFuncSetAttribute(tc_attn, cudaFuncAttributeMaxDynamicSharedMemorySize, ATT_SMEM);
    cudaFuncSetAttribute(tc_gemm<GM_QKV>,  cudaFuncAttributeMaxDynamicSharedMemorySize, G_SMEM);
    cudaFuncSetAttribute(tc_gemm<GM_RES>,  cudaFuncAttributeMaxDynamicSharedMemorySize, G_SMEM);
    cudaFuncSetAttribute(tc_gemm<GM_MOE1>, cudaFuncAttributeMaxDynamicSharedMemorySize, G_SMEM);
    cudaFuncSetAttribute(tc_gemm<GM_MOE2>, cudaFuncAttributeMaxDynamicSharedMemorySize, G_SMEM);

    fp16 *p_xn, *p_xn2, *p_ctx, *p_wpt, *p_w1t, *p_w2t, *p_H;
    float *p_xn2f, *p_x2, *p_Y;
    cudaGetSymbolAddress((void**)&p_xn,   g_xn);
    cudaGetSymbolAddress((void**)&p_xn2,  g_xn2);
    cudaGetSymbolAddress((void**)&p_xn2f, g_xn2f);
    cudaGetSymbolAddress((void**)&p_ctx,  g_ctx);
    cudaGetSymbolAddress((void**)&p_x2,   g_x2);
    cudaGetSymbolAddress((void**)&p_wpt,  g_wpt);
    cudaGetSymbolAddress((void**)&p_w1t,  g_w1t);
    cudaGetSymbolAddress((void**)&p_w2t,  g_w2t);
    cudaGetSymbolAddress((void**)&p_H,    g_H);
    cudaGetSymbolAddress((void**)&p_Y,    g_Y);

    dim3 bt(256);
    wt_convert_kernel<<<dim3(DD/64, DD/64, 1), bt>>>(wq, p_wpt,           DD, DD);
    wt_convert_kernel<<<dim3(DD/64, DD/64, 1), bt>>>(wk, p_wpt + DD*DD,   DD, DD);
    wt_convert_kernel<<<dim3(DD/64, DD/64, 1), bt>>>(wv, p_wpt + 2*DD*DD, DD, DD);
    wt_convert_kernel<<<dim3(DD/64, DD/64, 1), bt>>>(wo, p_wpt + 3*DD*DD, DD, DD);

    rmsnorm_kernel<<<TT, 256>>>(x, ln1, nullptr, p_xn);

    // launch 5 (ncu -s 5): QKV projections
    tc_gemm<GM_QKV><<<dim3(DD/256, TT/128, 3), 256, G_SMEM>>>(
        p_xn, p_wpt, nullptr, nullptr, nullptr, TT, DD, DD);

    wt_convert_kernel<<<dim3(FF/64, DD/64, NE), bt>>>(w1, p_w1t, DD, FF);
    wt_convert_kernel<<<dim3(DD/64, FF/64, NE), bt>>>(w2, p_w2t, FF, DD);

    tc_attn<<<dim3(BB * NH, SS / 128), 256, ATT_SMEM>>>(p_ctx);

    tc_gemm<GM_RES><<<dim3(DD/256, TT/128, 1), 256, G_SMEM>>>(
        p_ctx, p_wpt + 3*DD*DD, p_x2, x, nullptr, TT, DD, DD);

    rmsnorm_kernel<<<TT, 256>>>(p_x2, ln2, p_xn2f, p_xn2);

    zero_cnt_kernel<<<1, 32>>>();
    router_kernel<<<TT, 32>>>(p_xn2f, wr);
    loss_kernel<<<1, 256>>>(out, out_size);

    tc_gemm<GM_MOE1><<<dim3(FF/256, TT/128, NE), 256, G_SMEM>>>(
        p_xn2, p_w1t, nullptr, nullptr, p_H, TT, FF, DD);
    tc_gemm<GM_MOE2><<<dim3(DD/256, TT/128, NE), 256, G_SMEM>>>(
        p_H, p_w2t, p_Y, nullptr, nullptr, TT, DD, FF);

    combine_kernel<<<(NMAIN + 255) / 256, 256>>>(out);
}

// round 11
// speedup vs baseline: 3.4206x; 1.0564x over previous
#include <cuda_runtime.h>
#include <cuda_fp16.h>
#include <math.h>
#include <stdint.h>

#define BB 2
#define SS 2048
#define DD 1024
#define NH 16
#define DH 64
#define NE 8
#define FF 4096
#define TT (BB*SS)
#define NMAIN (TT*DD)

typedef __half fp16;

__device__ fp16  g_xn[TT*DD];
__device__ float g_xn2f[TT*DD];
__device__ fp16  g_xn2[TT*DD];
__device__ fp16  g_qkv[3][(size_t)TT*DD];
__device__ fp16  g_ctx[TT*DD];
__device__ float g_x2[TT*DD];
__device__ fp16  g_wpt[4*DD*DD];
__device__ fp16  g_w1t[(size_t)NE*DD*FF];
__device__ fp16  g_w2t[(size_t)NE*DD*FF];
__device__ fp16  g_H[(size_t)NE*TT*FF];
__device__ fp16  g_Y[(size_t)NE*TT*DD];
__device__ float g_probs[TT*NE];
__device__ float g_zz[TT];
__device__ int   g_cnt[NE];
__device__ int   g_rowlist[NE*TT];
__device__ int   g_slot_e[2*TT];
__device__ int   g_slot_r[2*TT];
__device__ float g_slot_w[2*TT];

__device__ __forceinline__ uint32_t smem_u32(const void* p) {
    uint32_t a;
    asm("{ .reg .u64 t; cvta.to.shared.u64 t, %1; cvt.u32.u64 %0, t; }" : "=r"(a) : "l"(p));
    return a;
}
__device__ __forceinline__ uint32_t elect1() {
    uint32_t p;
    asm volatile("{\n.reg .pred p;\nelect.sync _|p, 0xFFFFFFFF;\nselp.b32 %0, 1, 0, p;\n}" : "=r"(p));
    return p;
}
__device__ __forceinline__ void mbar_init(uint32_t a, uint32_t n) {
    asm volatile("mbarrier.init.shared.b64 [%0], %1;" :: "r"(a), "r"(n) : "memory");
}
__device__ __forceinline__ void mbar_wait(uint32_t a, uint32_t par) {
    asm volatile(
        "{\n.reg .pred P;\nLW%=:\n"
        "mbarrier.try_wait.parity.acquire.cta.shared::cta.b64 P, [%0], %1, 0x989680;\n"
        "@P bra LD%=;\nbra LW%=;\nLD%=:\n}" :: "r"(a), "r"(par) : "memory");
}
__device__ __forceinline__ uint64_t mk_desc(uint32_t addr) {
    return ((uint64_t)2 << 61) | ((uint64_t)1 << 46) | ((uint64_t)64 << 32)
         | ((uint64_t)1 << 16) | ((addr >> 4) & 0x3FFF);
}
__device__ __forceinline__ void tc_commit(uint32_t mbar) {
#if defined(__CUDA_ARCH_FEAT_SM103_ALL)
    asm volatile("tcgen05.commit.cta_group::1.mbarrier::arrive::one.shared::cluster.b64 [%0];"
                 :: "r"(mbar) : "memory");
#endif
}
__device__ __forceinline__ void mma_f16_ss(uint32_t d, uint64_t ad, uint64_t bd,
                                           uint32_t idesc, uint32_t en) {
#if defined(__CUDA_ARCH_FEAT_SM103_ALL)
    asm volatile(
        "{\n.reg .pred p;\nsetp.ne.u32 p, %4, 0;\n"
        "tcgen05.mma.cta_group::1.kind::f16 [%0], %1, %2, %3, {%5, %5, %5, %5}, p;\n}"
        :: "r"(d), "l"(ad), "l"(bd), "r"(idesc), "r"(en), "r"(0u) : "memory");
#endif
}

#if defined(__CUDA_ARCH_FEAT_SM103_ALL)
#define TC_ALLOC(sbaddr, n) \
    asm volatile("tcgen05.alloc.cta_group::1.sync.aligned.shared::cta.b32 [%0], %1;" \
                 :: "r"(sbaddr), "r"((uint32_t)(n)) : "memory")
#define TC_RELINQ() asm volatile("tcgen05.relinquish_alloc_permit.cta_group::1.sync.aligned;")
#define TC_DEALLOC(t, n) \
    asm volatile("tcgen05.dealloc.cta_group::1.sync.aligned.b32 %0, %1;" :: "r"(t), "r"((uint32_t)(n)))
#define TC_FENCE_AFTER()  asm volatile("tcgen05.fence::after_thread_sync;" ::: "memory")
#define TC_FENCE_BEFORE() asm volatile("tcgen05.fence::before_thread_sync;" ::: "memory")
#define TC_WAIT_LD()      asm volatile("tcgen05.wait::ld.sync.aligned;" ::: "memory")
#define TC_LD_X32(r, ta) \
    asm volatile( \
        "tcgen05.ld.sync.aligned.32x32b.x32.b32 " \
        "{%0, %1, %2, %3, %4, %5, %6, %7, %8, %9, %10, %11, %12, %13, %14, %15, " \
        " %16, %17, %18, %19, %20, %21, %22, %23, %24, %25, %26, %27, %28, %29, %30, %31}, [%32];" \
        : "=r"((r)[0]),  "=r"((r)[1]),  "=r"((r)[2]),  "=r"((r)[3]), \
          "=r"((r)[4]),  "=r"((r)[5]),  "=r"((r)[6]),  "=r"((r)[7]), \
          "=r"((r)[8]),  "=r"((r)[9]),  "=r"((r)[10]), "=r"((r)[11]), \
          "=r"((r)[12]), "=r"((r)[13]), "=r"((r)[14]), "=r"((r)[15]), \
          "=r"((r)[16]), "=r"((r)[17]), "=r"((r)[18]), "=r"((r)[19]), \
          "=r"((r)[20]), "=r"((r)[21]), "=r"((r)[22]), "=r"((r)[23]), \
          "=r"((r)[24]), "=r"((r)[25]), "=r"((r)[26]), "=r"((r)[27]), \
          "=r"((r)[28]), "=r"((r)[29]), "=r"((r)[30]), "=r"((r)[31]) \
        : "r"(ta))
#endif

__device__ __forceinline__ float gelu_tanh(float x) {
    float x3 = x * x * x;
    return 0.5f * x * (1.f + tanhf(0.7978845608028654f * (x + 0.044715f * x3)));
}
__device__ __forceinline__ uint32_t pack_h2(float a, float b) {
    __half2 h = __floats2half2_rn(a, b);
    return *(uint32_t*)&h;
}

// ---------------- rmsnorm ----------------
__global__ void rmsnorm_kernel(const float* __restrict__ x, const float* __restrict__ w,
                               float* __restrict__ yf, fp16* __restrict__ yh)
{
    int row = blockIdx.x, tid = threadIdx.x;
    const float* xr = x + (size_t)row * DD;
    int d4 = tid * 4;
    float4 xv = *(const float4*)(xr + d4);
    float s = xv.x * xv.x + xv.y * xv.y + xv.z * xv.z + xv.w * xv.w;
    __shared__ float red[8];
    for (int o = 16; o > 0; o >>= 1) s += __shfl_xor_sync(0xffffffffu, s, o);
    if ((tid & 31) == 0) red[tid >> 5] = s;
    __syncthreads();
    float tot = 0.f;
#pragma unroll
    for (int i = 0; i < 8; i++) tot += red[i];
    float inv = rsqrtf(tot / (float)DD + 1e-6f);
    float4 wv = *(const float4*)(w + d4);
    float v0 = xv.x * inv * wv.x, v1 = xv.y * inv * wv.y;
    float v2 = xv.z * inv * wv.z, v3 = xv.w * inv * wv.w;
    if (yf) *(float4*)(yf + (size_t)row * DD + d4) = make_float4(v0, v1, v2, v3);
    uint2 p; p.x = pack_h2(v0, v1); p.y = pack_h2(v2, v3);
    *(uint2*)(yh + (size_t)row * DD + d4) = p;
}

// ---------------- weight transpose -> fp16 ----------------
__global__ void wt_convert_kernel(const float* __restrict__ W,
                                  fp16* __restrict__ Th, int K, int N)
{
    __shared__ float tile[64][68];
    size_t zoff = (size_t)blockIdx.z * K * N;
    int n0 = blockIdx.x * 64, k0 = blockIdx.y * 64;
    int tx = threadIdx.x & 15, ty = threadIdx.x >> 4;
#pragma unroll
    for (int i = 0; i < 4; i++) {
        int r = ty + 16 * i;
        *(float4*)&tile[r][tx * 4] = *(const float4*)(W + zoff + (size_t)(k0 + r) * N + n0 + tx * 4);
    }
    __syncthreads();
#pragma unroll
    for (int i = 0; i < 4; i++) {
        int n = ty + 16 * i, kk = tx * 4;
        size_t idx = zoff + (size_t)(n0 + n) * K + k0 + kk;
        *(uint2*)(Th + idx) = make_uint2(pack_h2(tile[kk][n], tile[kk + 1][n]),
                                         pack_h2(tile[kk + 2][n], tile[kk + 3][n]));
    }
}

#define GM_QKV  1
#define GM_RES  2
#define GM_MOE1 3
#define GM_MOE2 4
#define BUF_BYTES 65536
#define G_SMEM  (1024 + 2 * BUF_BYTES)   // 132096 -> 1 CTA/SM

// ---------------- tcgen05 GEMM: C[256x256], fp16, two accumulators ---------
template<int MODE>
__global__ void __launch_bounds__(256, 1)
tc_gemm(const fp16* __restrict__ A, const fp16* __restrict__ B0,
        float* __restrict__ Cf, const float* __restrict__ Res,
        fp16* __restrict__ Ch, int M, int N, int K)
{
#if defined(__CUDA_ARCH__)
    extern __shared__ char sm[];
    int tid = threadIdx.x;
    int e  = blockIdx.z;
    int m0 = blockIdx.y * 256, n0 = blockIdx.x * 256;
    int Me = M;
    const fp16* B = B0;
    if (MODE == GM_MOE1 || MODE == GM_MOE2) {
        Me = g_cnt[e];
        if (m0 >= Me) return;
        B += (size_t)e * (size_t)K * N;
    } else if (MODE == GM_QKV) {
        B += (size_t)e * (size_t)K * N;
    }

#if defined(__CUDA_ARCH_FEAT_SM103_ALL)
    uint32_t sb = smem_u32(sm);
    int wid = tid >> 5, lid = tid & 31;
    int nk = K / 64;

    // A: 256 rows at tb (32KB, SW128 rows of 128B); B: 256 rows at tb+32768
    auto issue_fill = [&](int kc, int bufi) {
        uint32_t tb = sb + 1024 + (uint32_t)bufi * BUF_BYTES;
#pragma unroll
        for (int it = 0; it < 2; it++) {
            int task = tid + it * 256;
            if (task < 256) {
                int gr = m0 + task;
                bool val = gr < Me;
                size_t ri = 0;
                if (val) {
                    if (MODE == GM_MOE1)      ri = (size_t)g_rowlist[e * TT + gr];
                    else if (MODE == GM_MOE2) ri = (size_t)e * TT + gr;
                    else                      ri = (size_t)gr;
                }
                const char* src = (const char*)(A + ri * (size_t)K + kc * 64);
                uint32_t sz = val ? 16u : 0u;
#pragma unroll
                for (int j = 0; j < 8; j++) {
                    uint32_t off = (uint32_t)task * 128u + j * 16u;
                    uint32_t swz = off ^ ((off >> 3) & 0x70);
                    asm volatile("cp.async.cg.shared.global [%0], [%1], 16, %2;"
                                 :: "r"(tb + swz), "l"(src + j * 16), "r"(sz) : "memory");
                }
            } else {
                int row = task - 256;
                const char* src = (const char*)(B + (size_t)(n0 + row) * K + kc * 64);
#pragma unroll
                for (int j = 0; j < 8; j++) {
                    uint32_t off = (uint32_t)row * 128u + j * 16u;
                    uint32_t swz = off ^ ((off >> 3) & 0x70);
                    asm volatile("cp.async.cg.shared.global [%0], [%1], 16;"
                                 :: "r"(tb + 32768 + swz), "l"(src + j * 16) : "memory");
                }
            }
        }
        asm volatile("cp.async.commit_group;" ::: "memory");
    };

    issue_fill(0, 0);
    if (nk > 1) issue_fill(1, 1);

    if (wid == 0) { TC_ALLOC(sb, 512); TC_RELINQ(); }
    if (tid == 0) { mbar_init(sb + 8, 1); mbar_init(sb + 16, 1); }
    __syncthreads();
    uint32_t tmem;
    asm volatile("ld.shared.b32 %0, [%1];" : "=r"(tmem) : "r"(sb));

    const uint32_t IDESC = (1u << 4) | (32u << 17) | (8u << 24);   // f16, N=256, M=128
    int ph0 = 0, ph1 = 0;
    for (int kc = 0; kc < nk; kc++) {
        int b = kc & 1;
        if (kc >= 1 && kc + 1 < nk) {
            int nb = 1 - b;
            if (nb == 0) { mbar_wait(sb + 8,  (uint32_t)(ph0 & 1)); ph0++; }
            else         { mbar_wait(sb + 16, (uint32_t)(ph1 & 1)); ph1++; }
            issue_fill(kc + 1, nb);
        }
        if (kc + 1 < nk) asm volatile("cp.async.wait_group 1;" ::: "memory");
        else             asm volatile("cp.async.wait_group 0;" ::: "memory");
        asm volatile("fence.proxy.async.shared::cta;" ::: "memory");
        __syncthreads();
        if (wid == 0 && elect1()) {
            uint32_t tb = sb + 1024 + (uint32_t)b * BUF_BYTES;
            uint64_t dA0 = mk_desc(tb);
            uint64_t dA1 = mk_desc(tb + 16384);   // rows 128-255
            uint64_t dB  = mk_desc(tb + 32768);
#pragma unroll
            for (int s = 0; s < 4; s++) {
                uint32_t en0 = (kc == 0 && s == 0) ? 0u : 1u;
                mma_f16_ss(tmem,       dA0 + 2 * s, dB + 2 * s, IDESC, en0);
                mma_f16_ss(tmem + 256, dA1 + 2 * s, dB + 2 * s, IDESC, en0);
            }
            tc_commit(sb + 8 + b * 8);
        }
    }
    {
        int lb = (nk - 1) & 1;
        if (lb == 0) mbar_wait(sb + 8,  (uint32_t)(ph0 & 1));
        else         mbar_wait(sb + 16, (uint32_t)(ph1 & 1));
    }
    TC_FENCE_AFTER();

    int rw = wid & 3, cw = wid >> 2;
    float* Cs = (float*)(sm + 1024);
#pragma unroll 1
    for (int rb = 0; rb < 2; rb++) {
        int mb = m0 + rb * 128;
        int rows_here = Me - mb;
        if (rows_here <= 0) break;
        if (rows_here > 128) rows_here = 128;
#pragma unroll 1
        for (int p = 0; p < 2; p++) {
            uint32_t d0[32], d1[32];
            TC_LD_X32(d0, tmem + rb * 256 + p * 128 + cw * 64);
            TC_LD_X32(d1, tmem + rb * 256 + p * 128 + cw * 64 + 32);
            TC_WAIT_LD();
            TC_FENCE_BEFORE();
            __syncthreads();
            {
                int rr = rw * 32 + lid, cb = cw * 64;
#pragma unroll
                for (int j = 0; j < 32; j++) {
                    Cs[rr * 129 + cb + j]      = __uint_as_float(d0[j]);
                    Cs[rr * 129 + cb + 32 + j] = __uint_as_float(d1[j]);
                }
            }
            __syncthreads();
#pragma unroll 4
            for (int it = 0; it < 16; it++) {
                int idx4 = (it * 256 + tid) * 4;
                int rr = idx4 >> 7, cc = idx4 & 127;
                if (rr >= rows_here) continue;
                float v0 = Cs[rr * 129 + cc + 0], v1 = Cs[rr * 129 + cc + 1];
                float v2 = Cs[rr * 129 + cc + 2], v3 = Cs[rr * 129 + cc + 3];
                int colb = n0 + p * 128 + cc;
                if (MODE == GM_RES) {
                    size_t o = (size_t)(mb + rr) * N + colb;
                    float4 rs = *(const float4*)(Res + o);
                    *(float4*)(Cf + o) = make_float4(v0 + rs.x, v1 + rs.y, v2 + rs.z, v3 + rs.w);
                } else if (MODE == GM_MOE2) {
                    size_t o = ((size_t)e * TT + mb + rr) * N + colb;
                    uint2 ph; ph.x = pack_h2(v0, v1); ph.y = pack_h2(v2, v3);
                    *(uint2*)(g_Y + o) = ph;
                } else if (MODE == GM_MOE1) {
                    size_t o = ((size_t)e * TT + mb + rr) * N + colb;
                    uint2 ph;
                    ph.x = pack_h2(gelu_tanh(v0), gelu_tanh(v1));
                    ph.y = pack_h2(gelu_tanh(v2), gelu_tanh(v3));
                    *(uint2*)(Ch + o) = ph;
                } else {
                    int row = mb + rr;
                    int b2 = row >> 11, s5 = row & (SS - 1);
                    int h = colb >> 6, dh = colb & 63;
                    size_t o = (((size_t)(b2 * NH + h)) * SS + s5) * DH + dh;
                    uint2 ph; ph.x = pack_h2(v0, v1); ph.y = pack_h2(v2, v3);
                    *(uint2*)(g_qkv[e] + o) = ph;
                }
            }
            __syncthreads();
        }
    }
    if (wid == 0) { TC_DEALLOC(tmem, 512); }

#else
    // compact SIMT fallback (never runs when sm_103a SASS is loaded)
    for (int i = tid; i < 256 * 256; i += 256) {
        int rr = i >> 8, cc = i & 255;
        int row = m0 + rr;
        if (row >= Me) continue;
        size_t ri;
        if (MODE == GM_MOE1)      ri = (size_t)g_rowlist[e * TT + row];
        else if (MODE == GM_MOE2) ri = (size_t)e * TT + row;
        else                      ri = (size_t)row;
        float acc = 0.f;
        const fp16* ar = A + ri * (size_t)K;
        const fp16* br = B + (size_t)(n0 + cc) * K;
        for (int k = 0; k < K; k++)
            acc += __half2float(ar[k]) * __half2float(br[k]);
        if (MODE == GM_RES) { size_t o = (size_t)row * N + n0 + cc; Cf[o] = acc + Res[o]; }
        else if (MODE == GM_MOE2) g_Y[((size_t)e * TT + row) * N + n0 + cc] = __float2half_rn(acc);
        else if (MODE == GM_MOE1) Ch[((size_t)e * TT + row) * N + n0 + cc] = __float2half_rn(gelu_tanh(acc));
        else {
            int col = n0 + cc, b2 = row >> 11, s5 = row & (SS - 1);
            g_qkv[e][(((size_t)(b2 * NH + (col >> 6))) * SS + s5) * DH + (col & 63)] = __float2half_rn(acc);
        }
    }
#endif
#endif
}

// ---------------- tcgen05 flash attention (unchanged from passing R10) ------
#define SM_Q   1024
#define SM_K   17408
#define SM_VST 33792
#define SM_VT  50176
#define SM_P   66560
#define ATT_SMEM 100352

__global__ void __launch_bounds__(256, 2)
tc_attn(fp16* __restrict__ outh)
{
#if defined(__CUDA_ARCH__)
    extern __shared__ char sm[];
    int tid = threadIdx.x;
    int bh = blockIdx.x;
    int qt = blockIdx.y;

#if defined(__CUDA_ARCH_FEAT_SM103_ALL)
    uint32_t sb = smem_u32(sm);
    int wid = tid >> 5, lane = tid & 31;

    auto fill_kv = [&](int kt) {
        int arr = tid >> 7, r = tid & 127;
        const fp16* src = (arr == 0 ? g_qkv[1] : g_qkv[2]);
        uint32_t dstb = (arr == 0 ? sb + SM_K : sb + SM_VST);
        const char* s4 = (const char*)(src + ((size_t)bh * SS + kt * 128 + r) * DH);
        if (arr == 0) {
#pragma unroll
            for (int j = 0; j < 8; j++) {
                uint32_t off = (uint32_t)r * 128u + j * 16u;
                uint32_t swz = off ^ ((off >> 3) & 0x70);
                asm volatile("cp.async.cg.shared.global [%0], [%1], 16;"
                             :: "r"(dstb + swz), "l"(s4 + j * 16) : "memory");
            }
        } else {
#pragma unroll
            for (int j = 0; j < 8; j++)
                asm volatile("cp.async.cg.shared.global [%0], [%1], 16;"
                             :: "r"(dstb + (uint32_t)r * 128u + j * 16u), "l"(s4 + j * 16) : "memory");
        }
        asm volatile("cp.async.commit_group;" ::: "memory");
    };

    fill_kv(0);

    if (wid == 0) { TC_ALLOC(sb, 256); TC_RELINQ(); }
    if (tid == 0) { mbar_init(sb + 8, 1); mbar_init(sb + 16, 1); }
    __syncthreads();
    uint32_t tmem;
    asm volatile("ld.shared.b32 %0, [%1];" : "=r"(tmem) : "r"(sb));

    {
        int r = tid & 127, j0 = (tid >> 7) * 4;
        const uint4* s4 = (const uint4*)(g_qkv[0] + ((size_t)bh * SS + qt * 128 + r) * DH);
#pragma unroll
        for (int j = 0; j < 4; j++) {
            uint32_t off = (uint32_t)r * 128u + (j0 + j) * 16u;
            uint32_t swz = off ^ ((off >> 3) & 0x70);
            *(uint4*)(sm + SM_Q + swz) = s4[j0 + j];
        }
    }

    const uint32_t IDESC_S = (1u << 4) | (16u << 17) | (8u << 24);
    const uint32_t IDESC_O = (1u << 4) | (8u << 17)  | (8u << 24);
    int sph = 0, oph = 0;
    float lpart = 0.f;
    const int NKT = SS / 128;

    for (int kt = 0; kt < NKT; kt++) {
        if (kt > 0) { mbar_wait(sb + 16, (uint32_t)(oph & 1)); oph++; }
        asm volatile("cp.async.wait_group 0;" ::: "memory");
        asm volatile("fence.proxy.async.shared::cta;" ::: "memory");
        __syncthreads();

        if (wid == 0 && elect1()) {
            uint64_t dQ = mk_desc(sb + SM_Q);
            uint64_t dK = mk_desc(sb + SM_K);
#pragma unroll
            for (int ks = 0; ks < 4; ks++)
                mma_f16_ss(tmem, dQ + 2 * ks, dK + 2 * ks, IDESC_S, ks == 0 ? 0u : 1u);
            tc_commit(sb + 8);
        }

        {
            int d = tid & 63, shb = (tid >> 6) & 1, mh = tid >> 7;
            const unsigned short* vs = (const unsigned short*)(sm + SM_VST);
            char* vt = sm + SM_VT + shb * 8192;
#pragma unroll
            for (int i = 0; i < 16; i++) {
                int m = mh * 16 + i;
                int s0 = shb * 64 + 2 * m;
                uint32_t u = (uint32_t)vs[s0 * 64 + d] | ((uint32_t)vs[(s0 + 1) * 64 + d] << 16);
                uint32_t off = (uint32_t)d * 128u + m * 4u;
                uint32_t swz = off ^ ((off >> 3) & 0x70);
                *(uint32_t*)(vt + swz) = u;
            }
        }
        asm volatile("fence.proxy.async.shared::cta;" ::: "memory");
        __syncthreads();

        mbar_wait(sb + 8, (uint32_t)(sph & 1)); sph++;
        TC_FENCE_AFTER();

        if (kt + 1 < NKT) fill_kv(kt + 1);

        {
            int rw = wid & 3, cw = wid >> 2;
            uint32_t s0[32], s1[32];
            TC_LD_X32(s0, tmem + cw * 64);
            TC_LD_X32(s1, tmem + cw * 64 + 32);
            TC_WAIT_LD();
            TC_FENCE_BEFORE();
            int r = rw * 32 + lane;
            char* pb = sm + SM_P + cw * 16384;
#pragma unroll
            for (int m = 0; m < 32; m++) {
                int c0 = 2 * m, c1 = 2 * m + 1;
                float a = __uint_as_float(c0 < 32 ? s0[c0] : s1[c0 - 32]);
                float b = __uint_as_float(c1 < 32 ? s0[c1] : s1[c1 - 32]);
                float pa = __expf(a * 0.125f);
                float pbv = __expf(b * 0.125f);
                lpart += pa + pbv;
                uint32_t off = (uint32_t)r * 128u + m * 4u;
                uint32_t swz = off ^ ((off >> 3) & 0x70);
                *(uint32_t*)(pb + swz) = pack_h2(pa, pbv);
            }
        }
        asm volatile("fence.proxy.async.shared::cta;" ::: "memory");
        __syncthreads();

        if (wid == 0 && elect1()) {
#pragma unroll
            for (int kb = 0; kb < 2; kb++) {
                uint64_t dP = mk_desc(sb + SM_P + kb * 16384);
                uint64_t dV = mk_desc(sb + SM_VT + kb * 8192);
#pragma unroll
                for (int ks = 0; ks < 4; ks++) {
                    uint32_t en0 = (kt == 0 && kb == 0 && ks == 0) ? 0u : 1u;
                    mma_f16_ss(tmem + 128, dP + 2 * ks, dV + 2 * ks, IDESC_O, en0);
                }
            }
            tc_commit(sb + 16);
        }
    }
    mbar_wait(sb + 16, (uint32_t)(oph & 1)); oph++;
    TC_FENCE_AFTER();

    float* lred = (float*)(sm + SM_P);
    lred[tid] = lpart;
    __syncthreads();
    if (wid < 4) {
        uint32_t o0[32], o1[32];
        TC_LD_X32(o0, tmem + 128);
        TC_LD_X32(o1, tmem + 160);
        TC_WAIT_LD();
        TC_FENCE_BEFORE();
        int r = wid * 32 + lane;
        float inv = 1.f / (lred[r] + lred[r + 128]);
        int b = bh >> 4, h = bh & 15;
        int s = qt * 128 + r;
        uint32_t* ph = (uint32_t*)(outh + ((size_t)(b * SS + s)) * DD + h * 64);
#pragma unroll
        for (int m = 0; m < 32; m++) {
            int c0 = 2 * m, c1 = 2 * m + 1;
            float v0 = __uint_as_float(c0 < 32 ? o0[c0] : o1[c0 - 32]) * inv;
            float v1 = __uint_as_float(c1 < 32 ? o0[c1] : o1[c1 - 32]) * inv;
            ph[m] = pack_h2(v0, v1);
        }
    }
    __syncthreads();
    if (wid == 0) { TC_DEALLOC(tmem, 256); }

#else
    if (tid < 128) {
        int r = qt * 128 + tid;
        const fp16* Q = g_qkv[0] + ((size_t)bh * SS + r) * DH;
        float acc[DH];
        for (int d = 0; d < DH; d++) acc[d] = 0.f;
        float l = 0.f;
        for (int s = 0; s < SS; s++) {
            const fp16* Kp = g_qkv[1] + ((size_t)bh * SS + s) * DH;
            const fp16* Vp = g_qkv[2] + ((size_t)bh * SS + s) * DH;
            float sc = 0.f;
            for (int d = 0; d < DH; d++) sc += __half2float(Q[d]) * __half2float(Kp[d]);
            float p = expf(sc * 0.125f);
            l += p;
            for (int d = 0; d < DH; d++) acc[d] += p * __half2float(Vp[d]);
        }
        int b = bh >> 4, h = bh & 15;
        fp16* o = outh + ((size_t)(b * SS + r)) * DD + h * 64;
        for (int d = 0; d < DH; d++) o[d] = __float2half_rn(acc[d] / l);
    }
#endif
#endif
}

// ---------------- router ----------------
__global__ void zero_cnt_kernel() { if (threadIdx.x < NE) g_cnt[threadIdx.x] = 0; }

__global__ void router_kernel(const float* __restrict__ xn2, const float* __restrict__ wr)
{
    int t = blockIdx.x, lane = threadIdx.x;
    float p[NE];
#pragma unroll
    for (int e = 0; e < NE; e++) p[e] = 0.f;
    const float* xr = xn2 + (size_t)t * DD;
    for (int d = lane; d < DD; d += 32) {
        float xv = xr[d];
        const float* wrow = wr + (size_t)d * NE;
#pragma unroll
        for (int e = 0; e < NE; e++) p[e] = fmaf(xv, wrow[e], p[e]);
    }
#pragma unroll
    for (int e = 0; e < NE; e++)
        for (int o = 16; o > 0; o >>= 1) p[e] += __shfl_xor_sync(0xffffffffu, p[e], o);
    if (lane == 0) {
        float m = p[0];
#pragma unroll
        for (int e = 1; e < NE; e++) m = fmaxf(m, p[e]);
        float pr[NE], sum = 0.f;
#pragma unroll
        for (int e = 0; e < NE; e++) { pr[e] = expf(p[e] - m); sum += pr[e]; }
        float inv = 1.f / sum;
#pragma unroll
        for (int e = 0; e < NE; e++) pr[e] *= inv;
        g_zz[t] = m + logf(sum);
#pragma unroll
        for (int e = 0; e < NE; e++) g_probs[t * NE + e] = pr[e];
        int i0 = 0; float v0 = pr[0];
#pragma unroll
        for (int e = 1; e < NE; e++) if (pr[e] > v0) { v0 = pr[e]; i0 = e; }
        int i1 = -1; float v1 = -1.f;
#pragma unroll
        for (int e = 0; e < NE; e++) { if (e == i0) continue; if (pr[e] > v1) { v1 = pr[e]; i1 = e; } }
        float w0 = v0 / (v0 + v1), w1 = v1 / (v0 + v1);
        int r0 = atomicAdd(&g_cnt[i0], 1); g_rowlist[i0 * TT + r0] = t;
        int r1 = atomicAdd(&g_cnt[i1], 1); g_rowlist[i1 * TT + r1] = t;
        g_slot_e[2 * t]     = i0; g_slot_r[2 * t]     = r0; g_slot_w[2 * t]     = w0;
        g_slot_e[2 * t + 1] = i1; g_slot_r[2 * t + 1] = r1; g_slot_w[2 * t + 1] = w1;
    }
}

// ---------------- loss ----------------
__global__ void loss_kernel(float* __restrict__ out, int out_size)
{
    int tid = threadIdx.x;
    __shared__ float red[256];
    __shared__ float sumsp[NE];
    __shared__ float sumz;
    float accp[NE];
#pragma unroll
    for (int e = 0; e < NE; e++) accp[e] = 0.f;
    float accz = 0.f;
    for (int t = tid; t < TT; t += 256) {
        float z = g_zz[t];
        accz += z * z;
#pragma unroll
        for (int e = 0; e < NE; e++) accp[e] += g_probs[t * NE + e];
    }
    red[tid] = accz; __syncthreads();
    for (int o = 128; o > 0; o >>= 1) { if (tid < o) red[tid] += red[tid + o]; __syncthreads(); }
    if (tid == 0) sumz = red[0];
    __syncthreads();
    for (int e = 0; e < NE; e++) {
        red[tid] = accp[e]; __syncthreads();
        for (int o = 128; o > 0; o >>= 1) { if (tid < o) red[tid] += red[tid + o]; __syncthreads(); }
        if (tid == 0) sumsp[e] = red[0];
        __syncthreads();
    }
    if (tid == 0) {
        float aux = 0.f;
        for (int e = 0; e < NE; e++)
            aux += ((float)g_cnt[e] / (float)TT) * (sumsp[e] / (float)TT);
        aux *= (float)NE / 2.f;
        float loss = aux + 0.001f * (sumz / (float)TT);
        for (int i = NMAIN; i < out_size; i++) out[i] = loss;
    }
}

// ---------------- combine (vectorized x4, Y fp16) ----------------
__global__ void combine_kernel(float* __restrict__ out)
{
    int idx4 = (blockIdx.x * 256 + threadIdx.x) * 4;
    if (idx4 >= NMAIN) return;
    int t = idx4 >> 10, d = idx4 & 1023;
    int e0 = g_slot_e[2 * t], r0 = g_slot_r[2 * t];
    int e1 = g_slot_e[2 * t + 1], r1 = g_slot_r[2 * t + 1];
    float w0 = g_slot_w[2 * t], w1 = g_slot_w[2 * t + 1];
    float4 xv = *(const float4*)(g_x2 + idx4);
    uint2 y0u = *(const uint2*)(g_Y + ((size_t)e0 * TT + r0) * DD + d);
    uint2 y1u = *(const uint2*)(g_Y + ((size_t)e1 * TT + r1) * DD + d);
    __half2 a0 = *(__half2*)&y0u.x, a1 = *(__half2*)&y0u.y;
    __half2 b0 = *(__half2*)&y1u.x, b1 = *(__half2*)&y1u.y;
    float4 r;
    r.x = xv.x + w0 * __low2float(a0)  + w1 * __low2float(b0);
    r.y = xv.y + w0 * __high2float(a0) + w1 * __high2float(b0);
    r.z = xv.z + w0 * __low2float(a1)  + w1 * __low2float(b1);
    r.w = xv.w + w0 * __high2float(a1) + w1 * __high2float(b1);
    *(float4*)(out + idx4) = r;
}

// ---------------- launch ----------------
extern "C" void kernel_launch(void* const* d_in, const int* in_sizes, int n_in,
                              void* d_out, int out_size)
{
    const float* x   = (const float*)d_in[0];
    const float* ln1 = (const float*)d_in[1];
    const float* ln2 = (const float*)d_in[2];
    const float* wq  = (const float*)d_in[3];
    const float* wk  = (const float*)d_in[4];
    const float* wv  = (const float*)d_in[5];
    const float* wo  = (const float*)d_in[6];
    const float* wr  = (const float*)d_in[7];
    const float* w1  = (const float*)d_in[8];
    const float* w2  = (const float*)d_in[9];
    float* out = (float*)d_out;

    cudaFuncSetAttribute(tc_attn, cudaFuncAttributeMaxDynamicSharedMemorySize, ATT_SMEM);
    cudaFuncSetAttribute(tc_gemm<GM_QKV>,  cudaFuncAttributeMaxDynamicSharedMemorySize, G_SMEM);
    cudaFuncSetAttribute(tc_gemm<GM_RES>,  cudaFuncAttributeMaxDynamicSharedMemorySize, G_SMEM);
    cudaFuncSetAttribute(tc_gemm<GM_MOE1>, cudaFuncAttributeMaxDynamicSharedMemorySize, G_SMEM);
    cudaFuncSetAttribute(tc_gemm<GM_MOE2>, cudaFuncAttributeMaxDynamicSharedMemorySize, G_SMEM);

    fp16 *p_xn, *p_xn2, *p_ctx, *p_wpt, *p_w1t, *p_w2t, *p_H;
    float *p_xn2f, *p_x2;
    cudaGetSymbolAddress((void**)&p_xn,   g_xn);
    cudaGetSymbolAddress((void**)&p_xn2,  g_xn2);
    cudaGetSymbolAddress((void**)&p_xn2f, g_xn2f);
    cudaGetSymbolAddress((void**)&p_ctx,  g_ctx);
    cudaGetSymbolAddress((void**)&p_x2,   g_x2);
    cudaGetSymbolAddress((void**)&p_wpt,  g_wpt);
    cudaGetSymbolAddress((void**)&p_w1t,  g_w1t);
    cudaGetSymbolAddress((void**)&p_w2t,  g_w2t);
    cudaGetSymbolAddress((void**)&p_H,    g_H);

    dim3 bt(256);
    wt_convert_kernel<<<dim3(DD/64, DD/64, 1), bt>>>(wq, p_wpt,           DD, DD);
    wt_convert_kernel<<<dim3(DD/64, DD/64, 1), bt>>>(wk, p_wpt + DD*DD,   DD, DD);
    wt_convert_kernel<<<dim3(DD/64, DD/64, 1), bt>>>(wv, p_wpt + 2*DD*DD, DD, DD);
    wt_convert_kernel<<<dim3(DD/64, DD/64, 1), bt>>>(wo, p_wpt + 3*DD*DD, DD, DD);

    rmsnorm_kernel<<<TT, 256>>>(x, ln1, nullptr, p_xn);

    // launch 5 (ncu -s 5): QKV projections, M=256 tiles
    tc_gemm<GM_QKV><<<dim3(DD/256, TT/256, 3), 256, G_SMEM>>>(
        p_xn, p_wpt, nullptr, nullptr, nullptr, TT, DD, DD);

    wt_convert_kernel<<<dim3(FF/64, DD/64, NE), bt>>>(w1, p_w1t, DD, FF);
    wt_convert_kernel<<<dim3(DD/64, FF/64, NE), bt>>>(w2, p_w2t, FF, DD);

    tc_attn<<<dim3(BB * NH, SS / 128), 256, ATT_SMEM>>>(p_ctx);

    tc_gemm<GM_RES><<<dim3(DD/256, TT/256, 1), 256, G_SMEM>>>(
        p_ctx, p_wpt + 3*DD*DD, p_x2, x, nullptr, TT, DD, DD);

    rmsnorm_kernel<<<TT, 256>>>(p_x2, ln2, p_xn2f, p_xn2);

    zero_cnt_kernel<<<1, 32>>>();
    router_kernel<<<TT, 32>>>(p_xn2f, wr);
    loss_kernel<<<1, 256>>>(out, out_size);

    tc_gemm<GM_MOE1><<<dim3(FF/256, TT/256, NE), 256, G_SMEM>>>(
        p_xn2, p_w1t, nullptr, nullptr, p_H, TT, FF, DD);
    tc_gemm<GM_MOE2><<<dim3(DD/256, TT/256, NE), 256, G_SMEM>>>(
        p_H, p_w2t, nullptr, nullptr, nullptr, TT, DD, FF);

    combine_kernel<<<(NMAIN/4 + 255) / 256, 256>>>(out);
}